// round 3
// baseline (speedup 1.0000x reference)
#include <cuda_runtime.h>
#include <cuda_bf16.h>
#include <cstdint>

// Problem constants (fixed by setup_inputs)
#define BATCH 4
#define SEQ   2048
#define CDIM  1024
#define NHEAD 16
#define HDIM  64
#define MROWS (BATCH * SEQ)          // 8192
#define Y_ELEMS ((size_t)MROWS * CDIM)       // 8,388,608
#define KV_ELEMS ((size_t)BATCH * NHEAD * SEQ * HDIM) // 8,388,608

// Scratch (device globals: allocation-free per harness rules)
__device__ float g_q[Y_ELEMS];   // Q in [B,H,T,D]
__device__ float g_y[Y_ELEMS];   // attention output in [B,T,C]

// ---------------------------------------------------------------------------
// GEMM: out[m,n] = sum_k A[m,k] * W[n,k] + bias[n]
// A: [M,1024] row-major, W: [1024,1024] row-major (K contiguous for both).
// layout==0: out is [M,1024] row-major
// layout==1: out is [B,H,T,D] with m=b*T+t, n=h*D+d
// Tile 128x128x16, 256 threads, 8x8 per thread (split 64+64 fragments).
// ---------------------------------------------------------------------------
__global__ __launch_bounds__(256) void gemm_kernel(
    const float* __restrict__ A, const float* __restrict__ W,
    const float* __restrict__ bias, float* __restrict__ out, int layout)
{
    __shared__ float As[16][129];  // [k][m] transposed
    __shared__ float Bs[16][129];  // [k][n] transposed

    const int tid = threadIdx.x;
    const int tx = tid & 15;       // n group
    const int ty = tid >> 4;       // m group
    const int mbase = blockIdx.y * 128;
    const int nbase = blockIdx.x * 128;

    const float* Ap = A + (size_t)mbase * CDIM;
    const float* Wp = W + (size_t)nbase * CDIM;

    float acc[8][8];
    #pragma unroll
    for (int i = 0; i < 8; i++)
        #pragma unroll
        for (int j = 0; j < 8; j++) acc[i][j] = 0.f;

    for (int kk = 0; kk < CDIM; kk += 16) {
        #pragma unroll
        for (int it = 0; it < 8; it++) {
            int idx = tid + it * 256;       // 0..2047
            int k = idx & 15;
            int r = idx >> 4;               // 0..127
            As[k][r] = Ap[(size_t)r * CDIM + kk + k];
            Bs[k][r] = Wp[(size_t)r * CDIM + kk + k];
        }
        __syncthreads();
        #pragma unroll
        for (int k = 0; k < 16; k++) {
            float a[8], b[8];
            #pragma unroll
            for (int i = 0; i < 4; i++) {
                a[i]     = As[k][ty * 4 + i];
                a[i + 4] = As[k][64 + ty * 4 + i];
                b[i]     = Bs[k][tx * 4 + i];
                b[i + 4] = Bs[k][64 + tx * 4 + i];
            }
            #pragma unroll
            for (int i = 0; i < 8; i++)
                #pragma unroll
                for (int j = 0; j < 8; j++)
                    acc[i][j] += a[i] * b[j];
        }
        __syncthreads();
    }

    #pragma unroll
    for (int i = 0; i < 8; i++) {
        int ml = (i < 4) ? (ty * 4 + i) : (64 + ty * 4 + (i - 4));
        int m = mbase + ml;
        #pragma unroll
        for (int j = 0; j < 8; j++) {
            int nl = (j < 4) ? (tx * 4 + j) : (64 + tx * 4 + (j - 4));
            int n = nbase + nl;
            float v = acc[i][j] + bias[n];
            if (layout == 0) {
                out[(size_t)m * CDIM + n] = v;
            } else {
                int b_ = m >> 11;           // m / SEQ
                int t  = m & 2047;
                int h  = n >> 6;            // n / HDIM
                int d  = n & 63;
                out[(((size_t)(b_ * NHEAD + h)) * SEQ + t) * HDIM + d] = v;
            }
        }
    }
}

// ---------------------------------------------------------------------------
// Causal flash attention (fp32, online softmax).
// Q,K,V: [B*H][T][64]. Output Y: [B,T,C] (= [B,T,H*D]).
// Block: 64 q-rows x 64 k-cols per tile, D=64. 128 threads, 4x8 reg tiles.
// ---------------------------------------------------------------------------
__global__ __launch_bounds__(128) void attn_kernel(
    const float* __restrict__ Q, const float* __restrict__ K,
    const float* __restrict__ V, float* __restrict__ Y)
{
    __shared__ float Qs[64][65];   // [d][m], pre-scaled by 1/sqrt(D)
    __shared__ float Ks[64][65];   // [d][n]
    __shared__ float Ps[64][65];   // [n][m]
    __shared__ float Vs[64][65];   // [n][d]

    const int tid = threadIdx.x;
    const int tx = tid & 7;        // col group (n or d), 0..7, 8 cols each
    const int ty = tid >> 3;       // row group (m), 0..15, 4 rows each
    const int qt = blockIdx.x;     // q tile index (0..31)
    const int bh = blockIdx.y;     // b*H + h
    const int qbase = qt * 64;

    const float* Qp = Q + (size_t)bh * SEQ * HDIM + (size_t)qbase * HDIM;
    const float* Kp = K + (size_t)bh * SEQ * HDIM;
    const float* Vp = V + (size_t)bh * SEQ * HDIM;

    // Load Q tile transposed + scaled
    for (int idx = tid; idx < 64 * 64; idx += 128) {
        int d = idx & 63, m = idx >> 6;
        Qs[d][m] = Qp[idx] * 0.125f;   // 1/sqrt(64)
    }

    float o[4][8];
    float mi[4], li[4];
    #pragma unroll
    for (int i = 0; i < 4; i++) {
        mi[i] = -1e30f; li[i] = 0.f;
        #pragma unroll
        for (int j = 0; j < 8; j++) o[i][j] = 0.f;
    }

    for (int jt = 0; jt <= qt; jt++) {
        __syncthreads();   // previous O-GEMM done with Ps/Vs/Ks
        const float* Kt = Kp + (size_t)jt * 64 * HDIM;
        const float* Vt = Vp + (size_t)jt * 64 * HDIM;
        for (int idx = tid; idx < 64 * 64; idx += 128) {
            int d = idx & 63, n = idx >> 6;
            Ks[d][n] = Kt[idx];
            Vs[n][d] = Vt[idx];
        }
        __syncthreads();

        // S = Qs^T * Ks  (64x64), each thread 4x8
        float s[4][8];
        #pragma unroll
        for (int i = 0; i < 4; i++)
            #pragma unroll
            for (int j = 0; j < 8; j++) s[i][j] = 0.f;

        #pragma unroll 8
        for (int d = 0; d < 64; d++) {
            float a[4], b[8];
            #pragma unroll
            for (int i = 0; i < 4; i++) a[i] = Qs[d][ty * 4 + i];
            #pragma unroll
            for (int j = 0; j < 8; j++) b[j] = Ks[d][tx * 8 + j];
            #pragma unroll
            for (int i = 0; i < 4; i++)
                #pragma unroll
                for (int j = 0; j < 8; j++)
                    s[i][j] += a[i] * b[j];
        }

        // Causal mask only on the diagonal tile
        if (jt == qt) {
            #pragma unroll
            for (int i = 0; i < 4; i++) {
                int ml = ty * 4 + i;
                #pragma unroll
                for (int j = 0; j < 8; j++) {
                    int nl = tx * 8 + j;
                    if (nl > ml) s[i][j] = -1e30f;
                }
            }
        }

        // Online softmax
        #pragma unroll
        for (int i = 0; i < 4; i++) {
            float rm = s[i][0];
            #pragma unroll
            for (int j = 1; j < 8; j++) rm = fmaxf(rm, s[i][j]);
            #pragma unroll
            for (int off = 1; off < 8; off <<= 1)
                rm = fmaxf(rm, __shfl_xor_sync(0xffffffffu, rm, off));
            float mn = fmaxf(mi[i], rm);
            float c = __expf(mi[i] - mn);
            float rs = 0.f;
            #pragma unroll
            for (int j = 0; j < 8; j++) {
                float p = __expf(s[i][j] - mn);
                s[i][j] = p;
                rs += p;
            }
            #pragma unroll
            for (int off = 1; off < 8; off <<= 1)
                rs += __shfl_xor_sync(0xffffffffu, rs, off);
            li[i] = li[i] * c + rs;
            mi[i] = mn;
            #pragma unroll
            for (int j = 0; j < 8; j++) o[i][j] *= c;
        }

        // Write P transposed [n][m]
        #pragma unroll
        for (int i = 0; i < 4; i++)
            #pragma unroll
            for (int j = 0; j < 8; j++)
                Ps[tx * 8 + j][ty * 4 + i] = s[i][j];
        __syncthreads();

        // O += P * V  (loop over n)
        #pragma unroll 8
        for (int n = 0; n < 64; n++) {
            float p[4], v[8];
            #pragma unroll
            for (int i = 0; i < 4; i++) p[i] = Ps[n][ty * 4 + i];
            #pragma unroll
            for (int j = 0; j < 8; j++) v[j] = Vs[n][tx * 8 + j];
            #pragma unroll
            for (int i = 0; i < 4; i++)
                #pragma unroll
                for (int j = 0; j < 8; j++)
                    o[i][j] += p[i] * v[j];
        }
    }

    // Normalize and write to [B,T,C]
    const int b_ = bh >> 4;
    const int h  = bh & 15;
    #pragma unroll
    for (int i = 0; i < 4; i++) {
        int t = qbase + ty * 4 + i;
        float inv = 1.f / li[i];
        size_t row = ((size_t)b_ * SEQ + t) * CDIM + (size_t)h * HDIM;
        #pragma unroll
        for (int j = 0; j < 8; j++)
            Y[row + tx * 8 + j] = o[i][j] * inv;
    }
}

// ---------------------------------------------------------------------------
// Launch: QKV GEMMs -> flash attention -> output projection.
// d_in order: x, Wq, bq, Wk, bk, Wv, bv, Wp, bp
// d_out: [ y (B*T*C) | present_k (B*H*T*D) | present_v (B*H*T*D) ]
// ---------------------------------------------------------------------------
extern "C" void kernel_launch(void* const* d_in, const int* in_sizes, int n_in,
                              void* d_out, int out_size)
{
    const float* x  = (const float*)d_in[0];
    const float* Wq = (const float*)d_in[1];
    const float* bq = (const float*)d_in[2];
    const float* Wk = (const float*)d_in[3];
    const float* bk = (const float*)d_in[4];
    const float* Wv = (const float*)d_in[5];
    const float* bv = (const float*)d_in[6];
    const float* Wp = (const float*)d_in[7];
    const float* bp = (const float*)d_in[8];

    float* out  = (float*)d_out;
    float* kout = out + Y_ELEMS;              // present[0] = k, [B,H,T,D]
    float* vout = out + Y_ELEMS + KV_ELEMS;   // present[1] = v

    float *qp = nullptr, *yp = nullptr;
    cudaGetSymbolAddress((void**)&qp, g_q);
    cudaGetSymbolAddress((void**)&yp, g_y);

    dim3 gg(CDIM / 128, MROWS / 128);   // (8, 64)
    gemm_kernel<<<gg, 256>>>(x, Wq, bq, qp,   1);
    gemm_kernel<<<gg, 256>>>(x, Wk, bk, kout, 1);
    gemm_kernel<<<gg, 256>>>(x, Wv, bv, vout, 1);

    attn_kernel<<<dim3(SEQ / 64, BATCH * NHEAD), 128>>>(qp, kout, vout, yp);

    gemm_kernel<<<gg, 256>>>(yp, Wp, bp, out, 0);
}

// round 5
// speedup vs baseline: 1.7451x; 1.7451x over previous
#include <cuda_runtime.h>
#include <cuda_bf16.h>
#include <cstdint>

// Problem constants (fixed by setup_inputs)
#define BATCH 4
#define SEQ   2048
#define CDIM  1024
#define NHEAD 16
#define HDIM  64
#define MROWS (BATCH * SEQ)          // 8192
#define K3    3072                   // split-bf16 tripled K
#define Y_ELEMS ((size_t)MROWS * CDIM)                  // 8,388,608
#define KV_ELEMS ((size_t)BATCH * NHEAD * SEQ * HDIM)   // 8,388,608

// ---------------------------------------------------------------------------
// Device scratch (allocation-free per harness rules)
// ---------------------------------------------------------------------------
__device__ __align__(256) float g_q[Y_ELEMS];                   // Q in [B,H,T,D]
__device__ __align__(256) float g_y[Y_ELEMS];                   // attn out [B,T,C]
__device__ __align__(256) __nv_bfloat16 g_a3[(size_t)MROWS * K3];    // A-side split bf16
__device__ __align__(256) __nv_bfloat16 g_w3[4][(size_t)CDIM * K3];  // Wq,Wk,Wv,Wp split

// ---------------------------------------------------------------------------
// PTX helpers (base-target safe: cp.async / ldmatrix / mma.sync only)
// ---------------------------------------------------------------------------
__device__ __forceinline__ uint32_t smem_to_u32(const void* p) {
    uint32_t a;
    asm("{ .reg .u64 t; cvta.to.shared.u64 t, %1; cvt.u32.u64 %0, t; }" : "=r"(a) : "l"(p));
    return a;
}

#define CP_ASYNC16(dst, src) \
    asm volatile("cp.async.cg.shared.global [%0], [%1], 16;" :: "r"(dst), "l"(src))
#define CP_COMMIT() asm volatile("cp.async.commit_group;" ::: "memory")
#define CP_WAIT1()  asm volatile("cp.async.wait_group 1;" ::: "memory")
#define CP_WAIT0()  asm volatile("cp.async.wait_group 0;" ::: "memory")

__device__ __forceinline__ void ldsm_x4(uint32_t addr, uint32_t* r) {
    asm volatile("ldmatrix.sync.aligned.m8n8.x4.shared.b16 {%0,%1,%2,%3}, [%4];"
                 : "=r"(r[0]), "=r"(r[1]), "=r"(r[2]), "=r"(r[3]) : "r"(addr));
}

__device__ __forceinline__ void mma16816(float* c, const uint32_t* a, const uint32_t* b) {
    asm volatile(
        "mma.sync.aligned.m16n8k16.row.col.f32.bf16.bf16.f32 "
        "{%0,%1,%2,%3}, {%4,%5,%6,%7}, {%8,%9}, {%0,%1,%2,%3};"
        : "+f"(c[0]), "+f"(c[1]), "+f"(c[2]), "+f"(c[3])
        : "r"(a[0]), "r"(a[1]), "r"(a[2]), "r"(a[3]), "r"(b[0]), "r"(b[1]));
}

// ---------------------------------------------------------------------------
// Split-bf16 conversion: src [rows][1024] fp32 -> dst [rows][3072] bf16.
// modeA=1: blocks (hi, lo, hi) ; modeA=0: blocks (hi, hi, lo)
// ---------------------------------------------------------------------------
__global__ __launch_bounds__(256) void conv_split_kernel(
    const float* __restrict__ src, __nv_bfloat16* __restrict__ dst,
    int total2, int modeA)
{
    int i = blockIdx.x * blockDim.x + threadIdx.x;
    if (i >= total2) return;
    int r = i >> 9;              // / 512 float2 per row
    int c = (i & 511) << 1;      // element col
    float2 v = reinterpret_cast<const float2*>(src)[i];
    __nv_bfloat16 h0 = __float2bfloat16(v.x);
    __nv_bfloat16 h1 = __float2bfloat16(v.y);
    __nv_bfloat16 l0 = __float2bfloat16(v.x - __bfloat162float(h0));
    __nv_bfloat16 l1 = __float2bfloat16(v.y - __bfloat162float(h1));
    __nv_bfloat162 hi = __nv_bfloat162(h0, h1);
    __nv_bfloat162 lo = __nv_bfloat162(l0, l1);
    __nv_bfloat162* base = reinterpret_cast<__nv_bfloat162*>(dst + (size_t)r * K3 + c);
    base[0]    = hi;                      // block 0: hi
    base[512]  = modeA ? lo : hi;         // block 1 (+1024 elems)
    base[1024] = modeA ? hi : lo;         // block 2 (+2048 elems)
}

// ---------------------------------------------------------------------------
// mma.sync split-bf16 GEMM: out[m,n] = sum_k A3[m,k]*W3[n,k] + bias[n]
// A3: [M][3072] bf16 K-major, W3: [1024][3072] bf16 K-major.
// CTA tile 128x128, 256 threads (8 warps 4x2), warp tile 32x64.
// K-chunk 64, double-buffered smem, XOR-swizzled 128B rows.
// layout==0: out [M,1024] row-major;  layout==1: out [B,H,T,D]
// ---------------------------------------------------------------------------
#define GSM_TOTAL 65536   // 2 ops * 2 bufs * 128 rows * 128B

__global__ __launch_bounds__(256) void gemm_bf16_kernel(
    const __nv_bfloat16* __restrict__ A3, const __nv_bfloat16* __restrict__ W3,
    const float* __restrict__ bias, float* __restrict__ out, int layout)
{
    extern __shared__ char smem[];
    const uint32_t sA = smem_to_u32(smem);            // 2 x 16KB
    const uint32_t sB = sA + 32768;                   // 2 x 16KB

    const int tid  = threadIdx.x;
    const int wid  = tid >> 5;
    const int lane = tid & 31;
    const int wm = wid >> 1;        // 0..3 -> m offset 32*wm
    const int wn = wid & 1;         // 0..1 -> n offset 64*wn
    const int mbase = blockIdx.y * 128;
    const int nbase = blockIdx.x * 128;

    const __nv_bfloat16* Ag = A3 + (size_t)mbase * K3;
    const __nv_bfloat16* Bg = W3 + (size_t)nbase * K3;

    float acc[2][8][4];
    #pragma unroll
    for (int i = 0; i < 2; i++)
        #pragma unroll
        for (int j = 0; j < 8; j++)
            #pragma unroll
            for (int q = 0; q < 4; q++) acc[i][j][q] = 0.f;

    // loader lane mapping: idx in [0,1024): r = idx&7, c = (idx>>3)&7, blk = idx>>6
    // row = blk*8 + r (so row&7 == r), phys chunk = c ^ r
    const int lr  = tid & 7;
    const int lc  = (tid >> 3) & 7;
    const int lb0 = tid >> 6;      // 0..3, +4 per t-step

    const int NITER = K3 / 64;     // 48

    // ---- chunk loader (A and B tiles; 4+4 cp.async16 per thread) ----
    auto load_chunk = [&](int it) {
        const int buf = it & 1;
        const size_t kofs = (size_t)it * 64;   // bf16 elements
        const uint32_t aBase = sA + buf * 16384;
        const uint32_t bBase = sB + buf * 16384;
        #pragma unroll
        for (int t = 0; t < 4; t++) {
            int row = (lb0 + t * 4) * 8 + lr;
            uint32_t doff = row * 128 + ((lc ^ lr) << 4);
            const __nv_bfloat16* asrc = Ag + (size_t)row * K3 + kofs + lc * 8;
            const __nv_bfloat16* bsrc = Bg + (size_t)row * K3 + kofs + lc * 8;
            CP_ASYNC16(aBase + doff, asrc);
            CP_ASYNC16(bBase + doff, bsrc);
        }
    };

    load_chunk(0);
    CP_COMMIT();

    for (int it = 0; it < NITER; ++it) {
        if (it + 1 < NITER) { load_chunk(it + 1); CP_COMMIT(); CP_WAIT1(); }
        else                { CP_WAIT0(); }
        __syncthreads();

        const int buf = it & 1;
        const uint32_t aBase = sA + buf * 16384;
        const uint32_t bBase = sB + buf * 16384;

        #pragma unroll
        for (int ks = 0; ks < 4; ks++) {
            // A fragments: 2 x m16 tiles
            uint32_t af[2][4];
            #pragma unroll
            for (int mi = 0; mi < 2; mi++) {
                int row = wm * 32 + mi * 16 + (lane & 15);
                int chunk = 2 * ks + (lane >> 4);
                uint32_t addr = aBase + row * 128 + ((chunk ^ (row & 7)) << 4);
                ldsm_x4(addr, af[mi]);
            }
            // B fragments: 8 x n8 tiles via 4 x ldmatrix.x4
            uint32_t bf[8][2];
            #pragma unroll
            for (int ni = 0; ni < 4; ni++) {
                int row = wn * 64 + ni * 16 + ((lane >> 4) << 3) + (lane & 7);
                int chunk = 2 * ks + ((lane >> 3) & 1);
                uint32_t addr = bBase + row * 128 + ((chunk ^ (row & 7)) << 4);
                uint32_t r4[4];
                ldsm_x4(addr, r4);
                bf[2 * ni][0]     = r4[0];
                bf[2 * ni][1]     = r4[1];
                bf[2 * ni + 1][0] = r4[2];
                bf[2 * ni + 1][1] = r4[3];
            }
            #pragma unroll
            for (int mi = 0; mi < 2; mi++)
                #pragma unroll
                for (int nj = 0; nj < 8; nj++)
                    mma16816(acc[mi][nj], af[mi], bf[nj]);
        }
        __syncthreads();
    }

    // ---- epilogue: bias + store ----
    const int qr = lane >> 2;        // 0..7
    const int qc = (lane & 3) * 2;   // 0,2,4,6
    #pragma unroll
    for (int mi = 0; mi < 2; mi++) {
        #pragma unroll
        for (int half = 0; half < 2; half++) {
            int m = mbase + wm * 32 + mi * 16 + qr + half * 8;
            int b_ = m >> 11, t = m & 2047;
            #pragma unroll
            for (int nj = 0; nj < 8; nj++) {
                int n = nbase + wn * 64 + nj * 8 + qc;
                float2 o;
                o.x = acc[mi][nj][half * 2 + 0] + bias[n];
                o.y = acc[mi][nj][half * 2 + 1] + bias[n + 1];
                if (layout == 0) {
                    *reinterpret_cast<float2*>(out + (size_t)m * CDIM + n) = o;
                } else {
                    int h = n >> 6, d = n & 63;
                    *reinterpret_cast<float2*>(
                        out + (((size_t)(b_ * NHEAD + h)) * SEQ + t) * HDIM + d) = o;
                }
            }
        }
    }
}

// ---------------------------------------------------------------------------
// Causal flash attention (fp32, online softmax) — unchanged (passing, R3).
// ---------------------------------------------------------------------------
__global__ __launch_bounds__(128) void attn_kernel(
    const float* __restrict__ Q, const float* __restrict__ K,
    const float* __restrict__ V, float* __restrict__ Y)
{
    __shared__ float Qs[64][65];
    __shared__ float Ks[64][65];
    __shared__ float Ps[64][65];
    __shared__ float Vs[64][65];

    const int tid = threadIdx.x;
    const int tx = tid & 7;
    const int ty = tid >> 3;
    const int qt = blockIdx.x;
    const int bh = blockIdx.y;
    const int qbase = qt * 64;

    const float* Qp = Q + (size_t)bh * SEQ * HDIM + (size_t)qbase * HDIM;
    const float* Kp = K + (size_t)bh * SEQ * HDIM;
    const float* Vp = V + (size_t)bh * SEQ * HDIM;

    for (int idx = tid; idx < 64 * 64; idx += 128) {
        int d = idx & 63, m = idx >> 6;
        Qs[d][m] = Qp[idx] * 0.125f;
    }

    float o[4][8];
    float mi[4], li[4];
    #pragma unroll
    for (int i = 0; i < 4; i++) {
        mi[i] = -1e30f; li[i] = 0.f;
        #pragma unroll
        for (int j = 0; j < 8; j++) o[i][j] = 0.f;
    }

    for (int jt = 0; jt <= qt; jt++) {
        __syncthreads();
        const float* Kt = Kp + (size_t)jt * 64 * HDIM;
        const float* Vt = Vp + (size_t)jt * 64 * HDIM;
        for (int idx = tid; idx < 64 * 64; idx += 128) {
            int d = idx & 63, n = idx >> 6;
            Ks[d][n] = Kt[idx];
            Vs[n][d] = Vt[idx];
        }
        __syncthreads();

        float s[4][8];
        #pragma unroll
        for (int i = 0; i < 4; i++)
            #pragma unroll
            for (int j = 0; j < 8; j++) s[i][j] = 0.f;

        #pragma unroll 8
        for (int d = 0; d < 64; d++) {
            float a[4], b[8];
            #pragma unroll
            for (int i = 0; i < 4; i++) a[i] = Qs[d][ty * 4 + i];
            #pragma unroll
            for (int j = 0; j < 8; j++) b[j] = Ks[d][tx * 8 + j];
            #pragma unroll
            for (int i = 0; i < 4; i++)
                #pragma unroll
                for (int j = 0; j < 8; j++)
                    s[i][j] += a[i] * b[j];
        }

        if (jt == qt) {
            #pragma unroll
            for (int i = 0; i < 4; i++) {
                int ml = ty * 4 + i;
                #pragma unroll
                for (int j = 0; j < 8; j++) {
                    int nl = tx * 8 + j;
                    if (nl > ml) s[i][j] = -1e30f;
                }
            }
        }

        #pragma unroll
        for (int i = 0; i < 4; i++) {
            float rm = s[i][0];
            #pragma unroll
            for (int j = 1; j < 8; j++) rm = fmaxf(rm, s[i][j]);
            #pragma unroll
            for (int off = 1; off < 8; off <<= 1)
                rm = fmaxf(rm, __shfl_xor_sync(0xffffffffu, rm, off));
            float mn = fmaxf(mi[i], rm);
            float c = __expf(mi[i] - mn);
            float rs = 0.f;
            #pragma unroll
            for (int j = 0; j < 8; j++) {
                float p = __expf(s[i][j] - mn);
                s[i][j] = p;
                rs += p;
            }
            #pragma unroll
            for (int off = 1; off < 8; off <<= 1)
                rs += __shfl_xor_sync(0xffffffffu, rs, off);
            li[i] = li[i] * c + rs;
            mi[i] = mn;
            #pragma unroll
            for (int j = 0; j < 8; j++) o[i][j] *= c;
        }

        #pragma unroll
        for (int i = 0; i < 4; i++)
            #pragma unroll
            for (int j = 0; j < 8; j++)
                Ps[tx * 8 + j][ty * 4 + i] = s[i][j];
        __syncthreads();

        #pragma unroll 8
        for (int n = 0; n < 64; n++) {
            float p[4], v[8];
            #pragma unroll
            for (int i = 0; i < 4; i++) p[i] = Ps[n][ty * 4 + i];
            #pragma unroll
            for (int j = 0; j < 8; j++) v[j] = Vs[n][tx * 8 + j];
            #pragma unroll
            for (int i = 0; i < 4; i++)
                #pragma unroll
                for (int j = 0; j < 8; j++)
                    o[i][j] += p[i] * v[j];
        }
    }

    const int b_ = bh >> 4;
    const int h  = bh & 15;
    #pragma unroll
    for (int i = 0; i < 4; i++) {
        int t = qbase + ty * 4 + i;
        float inv = 1.f / li[i];
        size_t row = ((size_t)b_ * SEQ + t) * CDIM + (size_t)h * HDIM;
        #pragma unroll
        for (int j = 0; j < 8; j++)
            Y[row + tx * 8 + j] = o[i][j] * inv;
    }
}

// ---------------------------------------------------------------------------
// Launch: convert -> 3 mma GEMMs -> flash attention -> convert -> proj GEMM
// d_in: x, Wq, bq, Wk, bk, Wv, bv, Wp, bp
// d_out: [ y | present_k | present_v ]
// ---------------------------------------------------------------------------
extern "C" void kernel_launch(void* const* d_in, const int* in_sizes, int n_in,
                              void* d_out, int out_size)
{
    const float* x  = (const float*)d_in[0];
    const float* Wq = (const float*)d_in[1];
    const float* bq = (const float*)d_in[2];
    const float* Wk = (const float*)d_in[3];
    const float* bk = (const float*)d_in[4];
    const float* Wv = (const float*)d_in[5];
    const float* bv = (const float*)d_in[6];
    const float* Wp = (const float*)d_in[7];
    const float* bp = (const float*)d_in[8];

    float* out  = (float*)d_out;
    float* kout = out + Y_ELEMS;
    float* vout = out + Y_ELEMS + KV_ELEMS;

    float *qp = nullptr, *yp = nullptr;
    __nv_bfloat16 *a3 = nullptr, *w3 = nullptr;
    cudaGetSymbolAddress((void**)&qp, g_q);
    cudaGetSymbolAddress((void**)&yp, g_y);
    cudaGetSymbolAddress((void**)&a3, g_a3);
    cudaGetSymbolAddress((void**)&w3, g_w3);

    cudaFuncSetAttribute(gemm_bf16_kernel,
                         cudaFuncAttributeMaxDynamicSharedMemorySize, GSM_TOTAL);

    const size_t wstride = (size_t)CDIM * K3;
    // Weight conversions (B-side: hi,hi,lo)
    {
        int total2 = CDIM * 512;
        int blocks = (total2 + 255) / 256;
        conv_split_kernel<<<blocks, 256>>>(Wq, w3 + 0 * wstride, total2, 0);
        conv_split_kernel<<<blocks, 256>>>(Wk, w3 + 1 * wstride, total2, 0);
        conv_split_kernel<<<blocks, 256>>>(Wv, w3 + 2 * wstride, total2, 0);
        conv_split_kernel<<<blocks, 256>>>(Wp, w3 + 3 * wstride, total2, 0);
    }
    // x conversion (A-side: hi,lo,hi)
    {
        int total2 = MROWS * 512;
        conv_split_kernel<<<(total2 + 255) / 256, 256>>>(x, a3, total2, 1);
    }

    dim3 gg(CDIM / 128, MROWS / 128);   // (8, 64)
    gemm_bf16_kernel<<<gg, 256, GSM_TOTAL>>>(a3, w3 + 0 * wstride, bq, qp,   1);
    gemm_bf16_kernel<<<gg, 256, GSM_TOTAL>>>(a3, w3 + 1 * wstride, bk, kout, 1);
    gemm_bf16_kernel<<<gg, 256, GSM_TOTAL>>>(a3, w3 + 2 * wstride, bv, vout, 1);

    attn_kernel<<<dim3(SEQ / 64, BATCH * NHEAD), 128>>>(qp, kout, vout, yp);

    // y conversion (A-side) into the same a3 buffer, then output projection
    {
        int total2 = MROWS * 512;
        conv_split_kernel<<<(total2 + 255) / 256, 256>>>(yp, a3, total2, 1);
    }
    gemm_bf16_kernel<<<gg, 256, GSM_TOTAL>>>(a3, w3 + 3 * wstride, bp, out, 0);
}

// round 6
// speedup vs baseline: 3.1138x; 1.7843x over previous
#include <cuda_runtime.h>
#include <cuda_bf16.h>
#include <cstdint>

// Problem constants (fixed by setup_inputs)
#define BATCH 4
#define SEQ   2048
#define CDIM  1024
#define NHEAD 16
#define HDIM  64
#define MROWS (BATCH * SEQ)          // 8192
#define K3    3072                   // split-bf16 tripled K (projections)
#define D3    192                    // split-bf16 tripled head dim (attention)
#define Y_ELEMS ((size_t)MROWS * CDIM)                  // 8,388,608
#define KV_ELEMS ((size_t)BATCH * NHEAD * SEQ * HDIM)   // 8,388,608

// exp2-folded softmax scale: S2 = (0.125 * log2 e) * (q.k)
#define QSCALE 0.18033688011112042f

// ---------------------------------------------------------------------------
// Device scratch (allocation-free per harness rules)
// ---------------------------------------------------------------------------
__device__ __align__(256) float g_y[Y_ELEMS];                        // attn out [B,T,C]
__device__ __align__(256) __nv_bfloat16 g_a3[(size_t)MROWS * K3];    // A-side split (x / y)
__device__ __align__(256) __nv_bfloat16 g_w3[4][(size_t)CDIM * K3];  // Wq,Wk,Wv,Wp split
__device__ __align__(256) __nv_bfloat16 g_q3[(size_t)KV_ELEMS * 3];  // Q split [B,H,T,192]
__device__ __align__(256) __nv_bfloat16 g_k3[(size_t)KV_ELEMS * 3];  // K split [B,H,T,192]

// ---------------------------------------------------------------------------
// PTX helpers (base-target safe: cp.async / ldmatrix / mma.sync only)
// ---------------------------------------------------------------------------
__device__ __forceinline__ uint32_t smem_to_u32(const void* p) {
    uint32_t a;
    asm("{ .reg .u64 t; cvta.to.shared.u64 t, %1; cvt.u32.u64 %0, t; }" : "=r"(a) : "l"(p));
    return a;
}

#define CP_ASYNC16(dst, src) \
    asm volatile("cp.async.cg.shared.global [%0], [%1], 16;" :: "r"(dst), "l"(src))
#define CP_COMMIT() asm volatile("cp.async.commit_group;" ::: "memory")
#define CP_WAIT1()  asm volatile("cp.async.wait_group 1;" ::: "memory")
#define CP_WAIT0()  asm volatile("cp.async.wait_group 0;" ::: "memory")

__device__ __forceinline__ void ldsm_x4(uint32_t addr, uint32_t* r) {
    asm volatile("ldmatrix.sync.aligned.m8n8.x4.shared.b16 {%0,%1,%2,%3}, [%4];"
                 : "=r"(r[0]), "=r"(r[1]), "=r"(r[2]), "=r"(r[3]) : "r"(addr));
}
__device__ __forceinline__ void ldsm_x4_t(uint32_t addr, uint32_t* r) {
    asm volatile("ldmatrix.sync.aligned.m8n8.x4.trans.shared.b16 {%0,%1,%2,%3}, [%4];"
                 : "=r"(r[0]), "=r"(r[1]), "=r"(r[2]), "=r"(r[3]) : "r"(addr));
}

__device__ __forceinline__ void mma16816(float* c, const uint32_t* a, const uint32_t* b) {
    asm volatile(
        "mma.sync.aligned.m16n8k16.row.col.f32.bf16.bf16.f32 "
        "{%0,%1,%2,%3}, {%4,%5,%6,%7}, {%8,%9}, {%0,%1,%2,%3};"
        : "+f"(c[0]), "+f"(c[1]), "+f"(c[2]), "+f"(c[3])
        : "r"(a[0]), "r"(a[1]), "r"(a[2]), "r"(a[3]), "r"(b[0]), "r"(b[1]));
}

// Split two fp32 into packed bf16 hi-pair / lo-pair (elem0 in low half).
__device__ __forceinline__ void split2(float x0, float x1, uint32_t& hp, uint32_t& lp) {
    __nv_bfloat16 h0 = __float2bfloat16(x0);
    __nv_bfloat16 h1 = __float2bfloat16(x1);
    float r0 = x0 - __bfloat162float(h0);
    float r1 = x1 - __bfloat162float(h1);
    __nv_bfloat162 hh(h0, h1);
    __nv_bfloat162 ll(__float2bfloat16(r0), __float2bfloat16(r1));
    hp = *reinterpret_cast<uint32_t*>(&hh);
    lp = *reinterpret_cast<uint32_t*>(&ll);
}

// ---------------------------------------------------------------------------
// Split-bf16 conversion: src [rows][1024] fp32 -> dst [rows][3072] bf16.
// modeA=1: blocks (hi, lo, hi) ; modeA=0: blocks (hi, hi, lo)
// ---------------------------------------------------------------------------
__global__ __launch_bounds__(256) void conv_split_kernel(
    const float* __restrict__ src, __nv_bfloat16* __restrict__ dst,
    int total2, int modeA)
{
    int i = blockIdx.x * blockDim.x + threadIdx.x;
    if (i >= total2) return;
    int r = i >> 9;
    int c = (i & 511) << 1;
    float2 v = reinterpret_cast<const float2*>(src)[i];
    uint32_t hp, lp;
    split2(v.x, v.y, hp, lp);
    uint32_t* base = reinterpret_cast<uint32_t*>(dst + (size_t)r * K3 + c);
    base[0]    = hp;
    base[512]  = modeA ? lp : hp;
    base[1024] = modeA ? hp : lp;
}

// ---------------------------------------------------------------------------
// mma.sync split-bf16 GEMM: out[m,n] = sum_k A3[m,k]*W3[n,k] + bias[n]
// layouts: 0 = fp32 [M,1024]; 1 = fp32 [B,H,T,D];
//          2 = bf16 split (hi,lo,hi)*QSCALE -> out2 [B,H,T,192]   (Q)
//          3 = fp32 [B,H,T,D] + bf16 split (hi,hi,lo) -> out2      (K)
// ---------------------------------------------------------------------------
#define GSM_TOTAL 65536

__global__ __launch_bounds__(256) void gemm_bf16_kernel(
    const __nv_bfloat16* __restrict__ A3, const __nv_bfloat16* __restrict__ W3,
    const float* __restrict__ bias, float* __restrict__ out,
    __nv_bfloat16* __restrict__ out2, int layout)
{
    extern __shared__ char smem[];
    const uint32_t sA = smem_to_u32(smem);
    const uint32_t sB = sA + 32768;

    const int tid  = threadIdx.x;
    const int wid  = tid >> 5;
    const int lane = tid & 31;
    const int wm = wid >> 1;
    const int wn = wid & 1;
    const int mbase = blockIdx.y * 128;
    const int nbase = blockIdx.x * 128;

    const __nv_bfloat16* Ag = A3 + (size_t)mbase * K3;
    const __nv_bfloat16* Bg = W3 + (size_t)nbase * K3;

    float acc[2][8][4];
    #pragma unroll
    for (int i = 0; i < 2; i++)
        #pragma unroll
        for (int j = 0; j < 8; j++)
            #pragma unroll
            for (int q = 0; q < 4; q++) acc[i][j][q] = 0.f;

    const int lr  = tid & 7;
    const int lc  = (tid >> 3) & 7;
    const int lb0 = tid >> 6;

    const int NITER = K3 / 64;

    auto load_chunk = [&](int it) {
        const int buf = it & 1;
        const size_t kofs = (size_t)it * 64;
        const uint32_t aBase = sA + buf * 16384;
        const uint32_t bBase = sB + buf * 16384;
        #pragma unroll
        for (int t = 0; t < 4; t++) {
            int row = (lb0 + t * 4) * 8 + lr;
            uint32_t doff = row * 128 + ((lc ^ lr) << 4);
            const __nv_bfloat16* asrc = Ag + (size_t)row * K3 + kofs + lc * 8;
            const __nv_bfloat16* bsrc = Bg + (size_t)row * K3 + kofs + lc * 8;
            CP_ASYNC16(aBase + doff, asrc);
            CP_ASYNC16(bBase + doff, bsrc);
        }
    };

    load_chunk(0);
    CP_COMMIT();

    for (int it = 0; it < NITER; ++it) {
        if (it + 1 < NITER) { load_chunk(it + 1); CP_COMMIT(); CP_WAIT1(); }
        else                { CP_WAIT0(); }
        __syncthreads();

        const int buf = it & 1;
        const uint32_t aBase = sA + buf * 16384;
        const uint32_t bBase = sB + buf * 16384;

        #pragma unroll
        for (int ks = 0; ks < 4; ks++) {
            uint32_t af[2][4];
            #pragma unroll
            for (int mi = 0; mi < 2; mi++) {
                int row = wm * 32 + mi * 16 + (lane & 15);
                int chunk = 2 * ks + (lane >> 4);
                uint32_t addr = aBase + row * 128 + ((chunk ^ (row & 7)) << 4);
                ldsm_x4(addr, af[mi]);
            }
            uint32_t bf[8][2];
            #pragma unroll
            for (int ni = 0; ni < 4; ni++) {
                int row = wn * 64 + ni * 16 + ((lane >> 4) << 3) + (lane & 7);
                int chunk = 2 * ks + ((lane >> 3) & 1);
                uint32_t addr = bBase + row * 128 + ((chunk ^ (row & 7)) << 4);
                uint32_t r4[4];
                ldsm_x4(addr, r4);
                bf[2 * ni][0]     = r4[0];
                bf[2 * ni][1]     = r4[1];
                bf[2 * ni + 1][0] = r4[2];
                bf[2 * ni + 1][1] = r4[3];
            }
            #pragma unroll
            for (int mi = 0; mi < 2; mi++)
                #pragma unroll
                for (int nj = 0; nj < 8; nj++)
                    mma16816(acc[mi][nj], af[mi], bf[nj]);
        }
        __syncthreads();
    }

    const int qr = lane >> 2;
    const int qc = (lane & 3) * 2;
    #pragma unroll
    for (int mi = 0; mi < 2; mi++) {
        #pragma unroll
        for (int half = 0; half < 2; half++) {
            int m = mbase + wm * 32 + mi * 16 + qr + half * 8;
            int b_ = m >> 11, t = m & 2047;
            #pragma unroll
            for (int nj = 0; nj < 8; nj++) {
                int n = nbase + wn * 64 + nj * 8 + qc;
                float vx = acc[mi][nj][half * 2 + 0] + bias[n];
                float vy = acc[mi][nj][half * 2 + 1] + bias[n + 1];
                if (layout == 2) { vx *= QSCALE; vy *= QSCALE; }
                if (layout == 0) {
                    float2 o{vx, vy};
                    *reinterpret_cast<float2*>(out + (size_t)m * CDIM + n) = o;
                } else if (layout == 1 || layout == 3) {
                    int h = n >> 6, d = n & 63;
                    float2 o{vx, vy};
                    *reinterpret_cast<float2*>(
                        out + (((size_t)(b_ * NHEAD + h)) * SEQ + t) * HDIM + d) = o;
                }
                if (layout >= 2) {
                    uint32_t hp, lp;
                    split2(vx, vy, hp, lp);
                    int h = n >> 6, d = n & 63;
                    size_t base2 = (((size_t)(b_ * NHEAD + h)) * SEQ + t) * D3 + d;
                    *reinterpret_cast<uint32_t*>(out2 + base2)       = hp;
                    *reinterpret_cast<uint32_t*>(out2 + base2 + 64)  = (layout == 2) ? lp : hp;
                    *reinterpret_cast<uint32_t*>(out2 + base2 + 128) = (layout == 2) ? hp : lp;
                }
            }
        }
    }
}

// ---------------------------------------------------------------------------
// HMMA causal flash attention.
// Q3: [B,H,T,192] bf16 split (scaled), K3: [B,H,T,192] bf16 split, V fp32 [B,H,T,64].
// BM=BN=64, 128 threads (4 warps x 16 q-rows). Output g_y [B,T,C] fp32.
// smem: Qs 24K | Ks 2x24K | Vstage 16K | Vh 8K | Vl 8K = 104K
// ---------------------------------------------------------------------------
#define QS_OFF   0
#define KS_OFF   24576
#define VST_OFF  73728
#define VH_OFF   90112
#define VL_OFF   98304
#define ATTN_SMEM 106496

__global__ __launch_bounds__(128) void attn_kernel(
    const __nv_bfloat16* __restrict__ Q3, const __nv_bfloat16* __restrict__ K3g,
    const float* __restrict__ V, float* __restrict__ Y)
{
    extern __shared__ char smem[];
    const uint32_t sm = smem_to_u32(smem);
    const uint32_t QS = sm + QS_OFF;
    const uint32_t KS = sm + KS_OFF;
    const uint32_t VST = sm + VST_OFF;
    const uint32_t VH = sm + VH_OFF;
    const uint32_t VL = sm + VL_OFF;

    const int tid = threadIdx.x;
    const int w = tid >> 5;
    const int lane = tid & 31;
    const int qt = blockIdx.x;          // 0..31
    const int bh = blockIdx.y;          // 0..63
    const int qbase = qt * 64;

    const __nv_bfloat16* Qg = Q3 + ((size_t)bh * SEQ + qbase) * D3;
    const __nv_bfloat16* Kg = K3g + (size_t)bh * SEQ * D3;
    const float* Vg = V + (size_t)bh * SEQ * HDIM;

    // ---- loaders ----
    auto load_q = [&]() {
        #pragma unroll
        for (int i = 0; i < 12; i++) {
            int g = tid + i * 128;          // 0..1535
            int r = g & 63, bc = g >> 6;    // bc 0..23
            int b = bc >> 3, c = bc & 7;
            const __nv_bfloat16* src = Qg + (size_t)r * D3 + b * 64 + c * 8;
            uint32_t dst = QS + b * 8192 + r * 128 + ((c ^ (r & 7)) << 4);
            CP_ASYNC16(dst, src);
        }
    };
    auto load_k = [&](int jt, int buf) {
        const __nv_bfloat16* base = Kg + (size_t)jt * 64 * D3;
        uint32_t kb = KS + buf * 24576;
        #pragma unroll
        for (int i = 0; i < 12; i++) {
            int g = tid + i * 128;
            int r = g & 63, bc = g >> 6;
            int b = bc >> 3, c = bc & 7;
            const __nv_bfloat16* src = base + (size_t)r * D3 + b * 64 + c * 8;
            uint32_t dst = kb + b * 8192 + r * 128 + ((c ^ (r & 7)) << 4);
            CP_ASYNC16(dst, src);
        }
    };
    auto load_v_stage = [&](int jt) {
        const float* base = Vg + (size_t)jt * 64 * HDIM;
        #pragma unroll
        for (int i = 0; i < 8; i++) {
            int g = tid + i * 128;          // 0..1023
            int r = g >> 4, c = g & 15;
            CP_ASYNC16(VST + r * 256 + c * 16, base + (size_t)r * HDIM + c * 4);
        }
    };

    load_q();
    load_k(0, 0);
    load_v_stage(0);
    CP_COMMIT();

    float o[8][4];
    #pragma unroll
    for (int j = 0; j < 8; j++)
        #pragma unroll
        for (int q = 0; q < 4; q++) o[j][q] = 0.f;
    float mi0 = -1e30f, mi1 = -1e30f, li0 = 0.f, li1 = 0.f;

    for (int jt = 0; jt <= qt; ++jt) {
        const int buf = jt & 1;
        if (jt < qt) { load_k(jt + 1, buf ^ 1); CP_COMMIT(); CP_WAIT1(); }
        else         { CP_WAIT0(); }
        __syncthreads();   // K[buf], Vstage ready; prev PV done (Vh/Vl free)

        // ---- S = Q . K^T over 192 split dims ----
        float s[8][4];
        #pragma unroll
        for (int j = 0; j < 8; j++)
            #pragma unroll
            for (int q = 0; q < 4; q++) s[j][q] = 0.f;

        const uint32_t kb = KS + buf * 24576;
        #pragma unroll
        for (int b = 0; b < 3; b++) {
            #pragma unroll
            for (int ks = 0; ks < 4; ks++) {
                uint32_t af[4];
                {
                    int row = w * 16 + (lane & 15);
                    int chunk = 2 * ks + (lane >> 4);
                    ldsm_x4(QS + b * 8192 + row * 128 + ((chunk ^ (row & 7)) << 4), af);
                }
                uint32_t bf[8][2];
                #pragma unroll
                for (int ni = 0; ni < 4; ni++) {
                    int row = ni * 16 + ((lane >> 4) << 3) + (lane & 7);
                    int chunk = 2 * ks + ((lane >> 3) & 1);
                    uint32_t r4[4];
                    ldsm_x4(kb + b * 8192 + row * 128 + ((chunk ^ (row & 7)) << 4), r4);
                    bf[2 * ni][0] = r4[0]; bf[2 * ni][1] = r4[1];
                    bf[2 * ni + 1][0] = r4[2]; bf[2 * ni + 1][1] = r4[3];
                }
                #pragma unroll
                for (int nj = 0; nj < 8; nj++)
                    mma16816(s[nj], af, bf[nj]);
            }
        }

        // ---- causal mask (diagonal tile only) ----
        if (jt == qt) {
            const int r0 = w * 16 + (lane >> 2);
            const int cb = 2 * (lane & 3);
            #pragma unroll
            for (int nj = 0; nj < 8; nj++) {
                int c0 = nj * 8 + cb;
                if (c0 > r0)     s[nj][0] = -1e30f;
                if (c0 + 1 > r0) s[nj][1] = -1e30f;
                if (c0 > r0 + 8)     s[nj][2] = -1e30f;
                if (c0 + 1 > r0 + 8) s[nj][3] = -1e30f;
            }
        }

        // ---- online softmax (base-2; scale folded into Q) ----
        float mx0 = -1e30f, mx1 = -1e30f;
        #pragma unroll
        for (int nj = 0; nj < 8; nj++) {
            mx0 = fmaxf(mx0, fmaxf(s[nj][0], s[nj][1]));
            mx1 = fmaxf(mx1, fmaxf(s[nj][2], s[nj][3]));
        }
        mx0 = fmaxf(mx0, __shfl_xor_sync(0xffffffffu, mx0, 1));
        mx0 = fmaxf(mx0, __shfl_xor_sync(0xffffffffu, mx0, 2));
        mx1 = fmaxf(mx1, __shfl_xor_sync(0xffffffffu, mx1, 1));
        mx1 = fmaxf(mx1, __shfl_xor_sync(0xffffffffu, mx1, 2));
        float mn0 = fmaxf(mi0, mx0), mn1 = fmaxf(mi1, mx1);
        float c0 = exp2f(mi0 - mn0), c1 = exp2f(mi1 - mn1);
        mi0 = mn0; mi1 = mn1;
        float rs0 = 0.f, rs1 = 0.f;
        #pragma unroll
        for (int nj = 0; nj < 8; nj++) {
            s[nj][0] = exp2f(s[nj][0] - mn0); rs0 += s[nj][0];
            s[nj][1] = exp2f(s[nj][1] - mn0); rs0 += s[nj][1];
            s[nj][2] = exp2f(s[nj][2] - mn1); rs1 += s[nj][2];
            s[nj][3] = exp2f(s[nj][3] - mn1); rs1 += s[nj][3];
        }
        rs0 += __shfl_xor_sync(0xffffffffu, rs0, 1);
        rs0 += __shfl_xor_sync(0xffffffffu, rs0, 2);
        rs1 += __shfl_xor_sync(0xffffffffu, rs1, 1);
        rs1 += __shfl_xor_sync(0xffffffffu, rs1, 2);
        li0 = li0 * c0 + rs0;
        li1 = li1 * c1 + rs1;
        #pragma unroll
        for (int dj = 0; dj < 8; dj++) {
            o[dj][0] *= c0; o[dj][1] *= c0;
            o[dj][2] *= c1; o[dj][3] *= c1;
        }

        // ---- convert V stage (fp32) -> Vh/Vl bf16 tiles ----
        #pragma unroll
        for (int i = 0; i < 4; i++) {
            int g = tid + i * 128;          // 0..511
            int r = g >> 3, c = g & 7;      // row, 8-elem chunk
            const float* sp = reinterpret_cast<const float*>(smem + VST_OFF) + r * 64 + c * 8;
            uint32_t hp[4], lp[4];
            #pragma unroll
            for (int e = 0; e < 4; e++)
                split2(sp[2 * e], sp[2 * e + 1], hp[e], lp[e]);
            uint32_t off = r * 128 + ((c ^ (r & 7)) << 4);
            *reinterpret_cast<uint4*>(smem + VH_OFF + off) = make_uint4(hp[0], hp[1], hp[2], hp[3]);
            *reinterpret_cast<uint4*>(smem + VL_OFF + off) = make_uint4(lp[0], lp[1], lp[2], lp[3]);
        }
        __syncthreads();   // Vh/Vl ready, Vstage free

        if (jt < qt) { load_v_stage(jt + 1); CP_COMMIT(); }

        // ---- O += P . V  (3-pass split) ----
        #pragma unroll
        for (int kc = 0; kc < 4; kc++) {
            uint32_t ah[4], al[4];
            split2(s[2 * kc][0],     s[2 * kc][1],     ah[0], al[0]);
            split2(s[2 * kc][2],     s[2 * kc][3],     ah[1], al[1]);
            split2(s[2 * kc + 1][0], s[2 * kc + 1][1], ah[2], al[2]);
            split2(s[2 * kc + 1][2], s[2 * kc + 1][3], ah[3], al[3]);
            #pragma unroll
            for (int dj2 = 0; dj2 < 4; dj2++) {
                int mm = lane >> 3, j = lane & 7;
                int row = kc * 16 + (mm & 1) * 8 + j;
                int chunk = 2 * dj2 + (mm >> 1);
                uint32_t off = row * 128 + ((chunk ^ (row & 7)) << 4);
                uint32_t bh4[4], bl4[4];
                ldsm_x4_t(VH + off, bh4);
                ldsm_x4_t(VL + off, bl4);
                mma16816(o[2 * dj2],     ah, &bh4[0]);
                mma16816(o[2 * dj2 + 1], ah, &bh4[2]);
                mma16816(o[2 * dj2],     al, &bh4[0]);
                mma16816(o[2 * dj2 + 1], al, &bh4[2]);
                mma16816(o[2 * dj2],     ah, &bl4[0]);
                mma16816(o[2 * dj2 + 1], ah, &bl4[2]);
            }
        }
    }

    // ---- normalize + store [B,T,C] ----
    const int b_ = bh >> 4;
    const int h  = bh & 15;
    const float inv0 = 1.f / li0, inv1 = 1.f / li1;
    const int r0 = qbase + w * 16 + (lane >> 2);
    const int cb = h * HDIM + 2 * (lane & 3);
    #pragma unroll
    for (int dj = 0; dj < 8; dj++) {
        int col = cb + dj * 8;
        float2 v0{o[dj][0] * inv0, o[dj][1] * inv0};
        float2 v1{o[dj][2] * inv1, o[dj][3] * inv1};
        *reinterpret_cast<float2*>(Y + ((size_t)b_ * SEQ + r0) * CDIM + col) = v0;
        *reinterpret_cast<float2*>(Y + ((size_t)b_ * SEQ + r0 + 8) * CDIM + col) = v1;
    }
}

// ---------------------------------------------------------------------------
// Launch graph
// d_in: x, Wq, bq, Wk, bk, Wv, bv, Wp, bp
// d_out: [ y | present_k | present_v ]
// ---------------------------------------------------------------------------
extern "C" void kernel_launch(void* const* d_in, const int* in_sizes, int n_in,
                              void* d_out, int out_size)
{
    const float* x  = (const float*)d_in[0];
    const float* Wq = (const float*)d_in[1];
    const float* bq = (const float*)d_in[2];
    const float* Wk = (const float*)d_in[3];
    const float* bk = (const float*)d_in[4];
    const float* Wv = (const float*)d_in[5];
    const float* bv = (const float*)d_in[6];
    const float* Wp = (const float*)d_in[7];
    const float* bp = (const float*)d_in[8];

    float* out  = (float*)d_out;
    float* kout = out + Y_ELEMS;
    float* vout = out + Y_ELEMS + KV_ELEMS;

    float* yp = nullptr;
    __nv_bfloat16 *a3 = nullptr, *w3 = nullptr, *q3 = nullptr, *k3 = nullptr;
    cudaGetSymbolAddress((void**)&yp, g_y);
    cudaGetSymbolAddress((void**)&a3, g_a3);
    cudaGetSymbolAddress((void**)&w3, g_w3);
    cudaGetSymbolAddress((void**)&q3, g_q3);
    cudaGetSymbolAddress((void**)&k3, g_k3);

    cudaFuncSetAttribute(gemm_bf16_kernel,
                         cudaFuncAttributeMaxDynamicSharedMemorySize, GSM_TOTAL);
    cudaFuncSetAttribute(attn_kernel,
                         cudaFuncAttributeMaxDynamicSharedMemorySize, ATTN_SMEM);

    const size_t wstride = (size_t)CDIM * K3;
    {
        int total2 = CDIM * 512;
        int blocks = (total2 + 255) / 256;
        conv_split_kernel<<<blocks, 256>>>(Wq, w3 + 0 * wstride, total2, 0);
        conv_split_kernel<<<blocks, 256>>>(Wk, w3 + 1 * wstride, total2, 0);
        conv_split_kernel<<<blocks, 256>>>(Wv, w3 + 2 * wstride, total2, 0);
        conv_split_kernel<<<blocks, 256>>>(Wp, w3 + 3 * wstride, total2, 0);
    }
    {
        int total2 = MROWS * 512;
        conv_split_kernel<<<(total2 + 255) / 256, 256>>>(x, a3, total2, 1);
    }

    dim3 gg(CDIM / 128, MROWS / 128);   // (8, 64)
    gemm_bf16_kernel<<<gg, 256, GSM_TOTAL>>>(a3, w3 + 0 * wstride, bq, out,  q3, 2);
    gemm_bf16_kernel<<<gg, 256, GSM_TOTAL>>>(a3, w3 + 1 * wstride, bk, kout, k3, 3);
    gemm_bf16_kernel<<<gg, 256, GSM_TOTAL>>>(a3, w3 + 2 * wstride, bv, vout, q3, 1);

    attn_kernel<<<dim3(SEQ / 64, BATCH * NHEAD), 128, ATTN_SMEM>>>(q3, k3, vout, yp);

    {
        int total2 = MROWS * 512;
        conv_split_kernel<<<(total2 + 255) / 256, 256>>>(yp, a3, total2, 1);
    }
    gemm_bf16_kernel<<<gg, 256, GSM_TOTAL>>>(a3, w3 + 3 * wstride, bp, out, q3, 0);
}

// round 8
// speedup vs baseline: 3.3665x; 1.0812x over previous
#include <cuda_runtime.h>
#include <cuda_bf16.h>
#include <cstdint>

// Problem constants (fixed by setup_inputs)
#define BATCH 4
#define SEQ   2048
#define CDIM  1024
#define NHEAD 16
#define HDIM  64
#define MROWS (BATCH * SEQ)          // 8192
#define K3    3072                   // split-bf16 tripled K (projections)
#define D3    192                    // split-bf16 tripled head dim (attention)
#define Y_ELEMS ((size_t)MROWS * CDIM)                  // 8,388,608
#define KV_ELEMS ((size_t)BATCH * NHEAD * SEQ * HDIM)   // 8,388,608

// exp2-folded softmax scale: S2 = (0.125 * log2 e) * (q.k)
#define QSCALE 0.18033688011112042f

// ---------------------------------------------------------------------------
// Device scratch (allocation-free per harness rules)
// ---------------------------------------------------------------------------
__device__ __align__(256) __nv_bfloat16 g_a3[(size_t)MROWS * K3];    // A-side split (x, then y)
__device__ __align__(256) __nv_bfloat16 g_w3[4][(size_t)CDIM * K3];  // Wq,Wk,Wv,Wp split (contiguous)
__device__ __align__(256) __nv_bfloat16 g_q3[(size_t)KV_ELEMS * 3];  // Q split [B,H,T,192]
__device__ __align__(256) __nv_bfloat16 g_k3[(size_t)KV_ELEMS * 3];  // K split [B,H,T,192]

// ---------------------------------------------------------------------------
// PTX helpers (base-target safe: cp.async / ldmatrix / mma.sync only)
// ---------------------------------------------------------------------------
__device__ __forceinline__ uint32_t smem_to_u32(const void* p) {
    uint32_t a;
    asm("{ .reg .u64 t; cvta.to.shared.u64 t, %1; cvt.u32.u64 %0, t; }" : "=r"(a) : "l"(p));
    return a;
}

#define CP_ASYNC16(dst, src) \
    asm volatile("cp.async.cg.shared.global [%0], [%1], 16;" :: "r"(dst), "l"(src))
#define CP_COMMIT() asm volatile("cp.async.commit_group;" ::: "memory")
#define CP_WAIT1()  asm volatile("cp.async.wait_group 1;" ::: "memory")
#define CP_WAIT0()  asm volatile("cp.async.wait_group 0;" ::: "memory")

__device__ __forceinline__ void ldsm_x4(uint32_t addr, uint32_t* r) {
    asm volatile("ldmatrix.sync.aligned.m8n8.x4.shared.b16 {%0,%1,%2,%3}, [%4];"
                 : "=r"(r[0]), "=r"(r[1]), "=r"(r[2]), "=r"(r[3]) : "r"(addr));
}
__device__ __forceinline__ void ldsm_x4_t(uint32_t addr, uint32_t* r) {
    asm volatile("ldmatrix.sync.aligned.m8n8.x4.trans.shared.b16 {%0,%1,%2,%3}, [%4];"
                 : "=r"(r[0]), "=r"(r[1]), "=r"(r[2]), "=r"(r[3]) : "r"(addr));
}

__device__ __forceinline__ void mma16816(float* c, const uint32_t* a, const uint32_t* b) {
    asm volatile(
        "mma.sync.aligned.m16n8k16.row.col.f32.bf16.bf16.f32 "
        "{%0,%1,%2,%3}, {%4,%5,%6,%7}, {%8,%9}, {%0,%1,%2,%3};"
        : "+f"(c[0]), "+f"(c[1]), "+f"(c[2]), "+f"(c[3])
        : "r"(a[0]), "r"(a[1]), "r"(a[2]), "r"(a[3]), "r"(b[0]), "r"(b[1]));
}

// Split two fp32 into packed bf16 hi-pair / lo-pair (elem0 in low half).
__device__ __forceinline__ void split2(float x0, float x1, uint32_t& hp, uint32_t& lp) {
    __nv_bfloat16 h0 = __float2bfloat16(x0);
    __nv_bfloat16 h1 = __float2bfloat16(x1);
    float r0 = x0 - __bfloat162float(h0);
    float r1 = x1 - __bfloat162float(h1);
    __nv_bfloat162 hh(h0, h1);
    __nv_bfloat162 ll(__float2bfloat16(r0), __float2bfloat16(r1));
    hp = *reinterpret_cast<uint32_t*>(&hh);
    lp = *reinterpret_cast<uint32_t*>(&ll);
}

// ---------------------------------------------------------------------------
// Split-bf16 conversion: src [rows][1024] fp32 -> dst [rows][3072] bf16.
// modeA=1: blocks (hi, lo, hi) ; modeA=0: blocks (hi, hi, lo)
// ---------------------------------------------------------------------------
__global__ __launch_bounds__(256) void conv_split_kernel(
    const float* __restrict__ src, __nv_bfloat16* __restrict__ dst,
    int total2, int modeA)
{
    int i = blockIdx.x * blockDim.x + threadIdx.x;
    if (i >= total2) return;
    int r = i >> 9;
    int c = (i & 511) << 1;
    float2 v = reinterpret_cast<const float2*>(src)[i];
    uint32_t hp, lp;
    split2(v.x, v.y, hp, lp);
    uint32_t* base = reinterpret_cast<uint32_t*>(dst + (size_t)r * K3 + c);
    base[0]    = hp;
    base[512]  = modeA ? lp : hp;
    base[1024] = modeA ? hp : lp;
}

// ---------------------------------------------------------------------------
// mma.sync split-bf16 GEMM: out = A3 @ W3^T + bias, 3-stage cp.async pipeline.
// A3: [M][3072] bf16 K-major, W3: [Nrows][3072] bf16 K-major.
// CTA tile 128x128, 256 threads (8 warps 4x2), warp tile 32x64.
// mode 0: proj  -> out0 fp32 [M,1024], bias b0 (grid.x = 8)
// mode 1: fused QKV over Nrows=3072 (grid.x = 24):
//         n<1024  : Q  -> (val+bq)*QSCALE split (hi,lo,hi) into q3 [B,H,T,192]
//         n<2048  : K  -> val+bk fp32 into out0 ([B,H,T,D]) + split (hi,hi,lo) into k3
//         else    : V  -> val+bv fp32 into out1 ([B,H,T,D])
// ---------------------------------------------------------------------------
#define GSM_TOTAL 98304   // 3 stages x (16KB A + 16KB B)

__global__ __launch_bounds__(256) void gemm_bf16_kernel(
    const __nv_bfloat16* __restrict__ A3, const __nv_bfloat16* __restrict__ W3,
    const float* __restrict__ b0, const float* __restrict__ b1,
    const float* __restrict__ b2,
    float* __restrict__ out0, float* __restrict__ out1,
    __nv_bfloat16* __restrict__ q3, __nv_bfloat16* __restrict__ k3,
    int mode)
{
    extern __shared__ char smem[];
    const uint32_t sA = smem_to_u32(smem);      // 3 x 16KB
    const uint32_t sB = sA + 49152;             // 3 x 16KB

    const int tid  = threadIdx.x;
    const int wid  = tid >> 5;
    const int lane = tid & 31;
    const int wm = wid >> 1;
    const int wn = wid & 1;
    const int mbase = blockIdx.y * 128;
    const int nbase = blockIdx.x * 128;

    const __nv_bfloat16* Ag = A3 + (size_t)mbase * K3;
    const __nv_bfloat16* Bg = W3 + (size_t)nbase * K3;

    float acc[2][8][4];
    #pragma unroll
    for (int i = 0; i < 2; i++)
        #pragma unroll
        for (int j = 0; j < 8; j++)
            #pragma unroll
            for (int q = 0; q < 4; q++) acc[i][j][q] = 0.f;

    const int lr  = tid & 7;
    const int lc  = (tid >> 3) & 7;
    const int lb0 = tid >> 6;

    const int NITER = K3 / 64;     // 48

    auto load_chunk = [&](int it, int slot) {
        const size_t kofs = (size_t)it * 64;
        const uint32_t aBase = sA + slot * 16384;
        const uint32_t bBase = sB + slot * 16384;
        #pragma unroll
        for (int t = 0; t < 4; t++) {
            int row = (lb0 + t * 4) * 8 + lr;
            uint32_t doff = row * 128 + ((lc ^ lr) << 4);
            const __nv_bfloat16* asrc = Ag + (size_t)row * K3 + kofs + lc * 8;
            const __nv_bfloat16* bsrc = Bg + (size_t)row * K3 + kofs + lc * 8;
            CP_ASYNC16(aBase + doff, asrc);
            CP_ASYNC16(bBase + doff, bsrc);
        }
    };

    load_chunk(0, 0); CP_COMMIT();
    load_chunk(1, 1); CP_COMMIT();

    int slot = 0;
    for (int it = 0; it < NITER; ++it) {
        CP_WAIT1();            // group `it` complete
        __syncthreads();       // all consumers done with slot being refilled
        int nslot = slot + 2; if (nslot >= 3) nslot -= 3;
        if (it + 2 < NITER) load_chunk(it + 2, nslot);
        CP_COMMIT();           // always commit (empty groups keep count uniform)

        const uint32_t aBase = sA + slot * 16384;
        const uint32_t bBase = sB + slot * 16384;

        #pragma unroll
        for (int ks = 0; ks < 4; ks++) {
            uint32_t af[2][4];
            #pragma unroll
            for (int mi = 0; mi < 2; mi++) {
                int row = wm * 32 + mi * 16 + (lane & 15);
                int chunk = 2 * ks + (lane >> 4);
                uint32_t addr = aBase + row * 128 + ((chunk ^ (row & 7)) << 4);
                ldsm_x4(addr, af[mi]);
            }
            uint32_t bf[8][2];
            #pragma unroll
            for (int ni = 0; ni < 4; ni++) {
                int row = wn * 64 + ni * 16 + ((lane >> 4) << 3) + (lane & 7);
                int chunk = 2 * ks + ((lane >> 3) & 1);
                uint32_t addr = bBase + row * 128 + ((chunk ^ (row & 7)) << 4);
                uint32_t r4[4];
                ldsm_x4(addr, r4);
                bf[2 * ni][0]     = r4[0];
                bf[2 * ni][1]     = r4[1];
                bf[2 * ni + 1][0] = r4[2];
                bf[2 * ni + 1][1] = r4[3];
            }
            #pragma unroll
            for (int mi = 0; mi < 2; mi++)
                #pragma unroll
                for (int nj = 0; nj < 8; nj++)
                    mma16816(acc[mi][nj], af[mi], bf[nj]);
        }
        if (++slot >= 3) slot = 0;
    }

    // ---- epilogue ----
    const int which = nbase >> 10;                  // uniform per CTA (mode 1)
    const float* bias = (mode == 0) ? b0 : (which == 0 ? b0 : (which == 1 ? b1 : b2));
    const int qr = lane >> 2;
    const int qc = (lane & 3) * 2;
    #pragma unroll
    for (int mi = 0; mi < 2; mi++) {
        #pragma unroll
        for (int half = 0; half < 2; half++) {
            int m = mbase + wm * 32 + mi * 16 + qr + half * 8;
            int b_ = m >> 11, t = m & 2047;
            #pragma unroll
            for (int nj = 0; nj < 8; nj++) {
                int ng = nbase + wn * 64 + nj * 8 + qc;
                int n  = ng & 1023;
                float vx = acc[mi][nj][half * 2 + 0] + bias[n];
                float vy = acc[mi][nj][half * 2 + 1] + bias[n + 1];
                if (mode == 0) {
                    float2 o{vx, vy};
                    *reinterpret_cast<float2*>(out0 + (size_t)m * CDIM + n) = o;
                } else {
                    int h = n >> 6, d = n & 63;
                    size_t bht = ((size_t)(b_ * NHEAD + h)) * SEQ + t;
                    if (which == 0) {
                        vx *= QSCALE; vy *= QSCALE;
                        uint32_t hp, lp;
                        split2(vx, vy, hp, lp);
                        size_t base2 = bht * D3 + d;
                        *reinterpret_cast<uint32_t*>(q3 + base2)       = hp;
                        *reinterpret_cast<uint32_t*>(q3 + base2 + 64)  = lp;
                        *reinterpret_cast<uint32_t*>(q3 + base2 + 128) = hp;
                    } else if (which == 1) {
                        float2 o{vx, vy};
                        *reinterpret_cast<float2*>(out0 + bht * HDIM + d) = o;
                        uint32_t hp, lp;
                        split2(vx, vy, hp, lp);
                        size_t base2 = bht * D3 + d;
                        *reinterpret_cast<uint32_t*>(k3 + base2)       = hp;
                        *reinterpret_cast<uint32_t*>(k3 + base2 + 64)  = hp;
                        *reinterpret_cast<uint32_t*>(k3 + base2 + 128) = lp;
                    } else {
                        float2 o{vx, vy};
                        *reinterpret_cast<float2*>(out1 + bht * HDIM + d) = o;
                    }
                }
            }
        }
    }
}

// ---------------------------------------------------------------------------
// HMMA causal flash attention.
// Q3: [B,H,T,192] bf16 split (scaled), K3: [B,H,T,192] bf16 split, V fp32 [B,H,T,64].
// BM=BN=64, 128 threads (4 warps x 16 q-rows).
// Output: split-bf16 (hi,lo,hi) rows of A3 [M][3072] for the proj GEMM.
// smem: Qs 24K | Ks 2x24K | Vstage 16K | Vh 8K | Vl 8K = 104K
// ---------------------------------------------------------------------------
#define QS_OFF   0
#define KS_OFF   24576
#define VST_OFF  73728
#define VH_OFF   90112
#define VL_OFF   98304
#define ATTN_SMEM 106496

__global__ __launch_bounds__(128) void attn_kernel(
    const __nv_bfloat16* __restrict__ Q3, const __nv_bfloat16* __restrict__ K3g,
    const float* __restrict__ V, __nv_bfloat16* __restrict__ Yd)
{
    extern __shared__ char smem[];
    const uint32_t sm = smem_to_u32(smem);
    const uint32_t QS = sm + QS_OFF;
    const uint32_t KS = sm + KS_OFF;
    const uint32_t VST = sm + VST_OFF;
    const uint32_t VH = sm + VH_OFF;
    const uint32_t VL = sm + VL_OFF;

    const int tid = threadIdx.x;
    const int w = tid >> 5;
    const int lane = tid & 31;
    const int qt = blockIdx.x;          // 0..31
    const int bh = blockIdx.y;          // 0..63
    const int qbase = qt * 64;

    const __nv_bfloat16* Qg = Q3 + ((size_t)bh * SEQ + qbase) * D3;
    const __nv_bfloat16* Kg = K3g + (size_t)bh * SEQ * D3;
    const float* Vg = V + (size_t)bh * SEQ * HDIM;

    auto load_q = [&]() {
        #pragma unroll
        for (int i = 0; i < 12; i++) {
            int g = tid + i * 128;
            int r = g & 63, bc = g >> 6;
            int b = bc >> 3, c = bc & 7;
            const __nv_bfloat16* src = Qg + (size_t)r * D3 + b * 64 + c * 8;
            uint32_t dst = QS + b * 8192 + r * 128 + ((c ^ (r & 7)) << 4);
            CP_ASYNC16(dst, src);
        }
    };
    auto load_k = [&](int jt, int buf) {
        const __nv_bfloat16* base = Kg + (size_t)jt * 64 * D3;
        uint32_t kb = KS + buf * 24576;
        #pragma unroll
        for (int i = 0; i < 12; i++) {
            int g = tid + i * 128;
            int r = g & 63, bc = g >> 6;
            int b = bc >> 3, c = bc & 7;
            const __nv_bfloat16* src = base + (size_t)r * D3 + b * 64 + c * 8;
            uint32_t dst = kb + b * 8192 + r * 128 + ((c ^ (r & 7)) << 4);
            CP_ASYNC16(dst, src);
        }
    };
    auto load_v_stage = [&](int jt) {
        const float* base = Vg + (size_t)jt * 64 * HDIM;
        #pragma unroll
        for (int i = 0; i < 8; i++) {
            int g = tid + i * 128;
            int r = g >> 4, c = g & 15;
            CP_ASYNC16(VST + r * 256 + c * 16, base + (size_t)r * HDIM + c * 4);
        }
    };

    load_q();
    load_k(0, 0);
    load_v_stage(0);
    CP_COMMIT();

    float o[8][4];
    #pragma unroll
    for (int j = 0; j < 8; j++)
        #pragma unroll
        for (int q = 0; q < 4; q++) o[j][q] = 0.f;
    float mi0 = -1e30f, mi1 = -1e30f, li0 = 0.f, li1 = 0.f;

    for (int jt = 0; jt <= qt; ++jt) {
        const int buf = jt & 1;
        if (jt < qt) { load_k(jt + 1, buf ^ 1); CP_COMMIT(); CP_WAIT1(); }
        else         { CP_WAIT0(); }
        __syncthreads();

        // ---- S = Q . K^T over 192 split dims ----
        float s[8][4];
        #pragma unroll
        for (int j = 0; j < 8; j++)
            #pragma unroll
            for (int q = 0; q < 4; q++) s[j][q] = 0.f;

        const uint32_t kb = KS + buf * 24576;
        #pragma unroll
        for (int b = 0; b < 3; b++) {
            #pragma unroll
            for (int ks = 0; ks < 4; ks++) {
                uint32_t af[4];
                {
                    int row = w * 16 + (lane & 15);
                    int chunk = 2 * ks + (lane >> 4);
                    ldsm_x4(QS + b * 8192 + row * 128 + ((chunk ^ (row & 7)) << 4), af);
                }
                uint32_t bf[8][2];
                #pragma unroll
                for (int ni = 0; ni < 4; ni++) {
                    int row = ni * 16 + ((lane >> 4) << 3) + (lane & 7);
                    int chunk = 2 * ks + ((lane >> 3) & 1);
                    uint32_t r4[4];
                    ldsm_x4(kb + b * 8192 + row * 128 + ((chunk ^ (row & 7)) << 4), r4);
                    bf[2 * ni][0] = r4[0]; bf[2 * ni][1] = r4[1];
                    bf[2 * ni + 1][0] = r4[2]; bf[2 * ni + 1][1] = r4[3];
                }
                #pragma unroll
                for (int nj = 0; nj < 8; nj++)
                    mma16816(s[nj], af, bf[nj]);
            }
        }

        // ---- causal mask (diagonal tile only) ----
        if (jt == qt) {
            const int r0 = w * 16 + (lane >> 2);
            const int cb = 2 * (lane & 3);
            #pragma unroll
            for (int nj = 0; nj < 8; nj++) {
                int c0 = nj * 8 + cb;
                if (c0 > r0)     s[nj][0] = -1e30f;
                if (c0 + 1 > r0) s[nj][1] = -1e30f;
                if (c0 > r0 + 8)     s[nj][2] = -1e30f;
                if (c0 + 1 > r0 + 8) s[nj][3] = -1e30f;
            }
        }

        // ---- online softmax (base-2; scale folded into Q) ----
        float mx0 = -1e30f, mx1 = -1e30f;
        #pragma unroll
        for (int nj = 0; nj < 8; nj++) {
            mx0 = fmaxf(mx0, fmaxf(s[nj][0], s[nj][1]));
            mx1 = fmaxf(mx1, fmaxf(s[nj][2], s[nj][3]));
        }
        mx0 = fmaxf(mx0, __shfl_xor_sync(0xffffffffu, mx0, 1));
        mx0 = fmaxf(mx0, __shfl_xor_sync(0xffffffffu, mx0, 2));
        mx1 = fmaxf(mx1, __shfl_xor_sync(0xffffffffu, mx1, 1));
        mx1 = fmaxf(mx1, __shfl_xor_sync(0xffffffffu, mx1, 2));
        float mn0 = fmaxf(mi0, mx0), mn1 = fmaxf(mi1, mx1);
        float c0 = exp2f(mi0 - mn0), c1 = exp2f(mi1 - mn1);
        mi0 = mn0; mi1 = mn1;
        float rs0 = 0.f, rs1 = 0.f;
        #pragma unroll
        for (int nj = 0; nj < 8; nj++) {
            s[nj][0] = exp2f(s[nj][0] - mn0); rs0 += s[nj][0];
            s[nj][1] = exp2f(s[nj][1] - mn0); rs0 += s[nj][1];
            s[nj][2] = exp2f(s[nj][2] - mn1); rs1 += s[nj][2];
            s[nj][3] = exp2f(s[nj][3] - mn1); rs1 += s[nj][3];
        }
        rs0 += __shfl_xor_sync(0xffffffffu, rs0, 1);
        rs0 += __shfl_xor_sync(0xffffffffu, rs0, 2);
        rs1 += __shfl_xor_sync(0xffffffffu, rs1, 1);
        rs1 += __shfl_xor_sync(0xffffffffu, rs1, 2);
        li0 = li0 * c0 + rs0;
        li1 = li1 * c1 + rs1;
        #pragma unroll
        for (int dj = 0; dj < 8; dj++) {
            o[dj][0] *= c0; o[dj][1] *= c0;
            o[dj][2] *= c1; o[dj][3] *= c1;
        }

        // ---- convert V stage (fp32) -> Vh/Vl bf16 tiles ----
        #pragma unroll
        for (int i = 0; i < 4; i++) {
            int g = tid + i * 128;
            int r = g >> 3, c = g & 7;
            const float* sp = reinterpret_cast<const float*>(smem + VST_OFF) + r * 64 + c * 8;
            uint32_t hp[4], lp[4];
            #pragma unroll
            for (int e = 0; e < 4; e++)
                split2(sp[2 * e], sp[2 * e + 1], hp[e], lp[e]);
            uint32_t off = r * 128 + ((c ^ (r & 7)) << 4);
            *reinterpret_cast<uint4*>(smem + VH_OFF + off) = make_uint4(hp[0], hp[1], hp[2], hp[3]);
            *reinterpret_cast<uint4*>(smem + VL_OFF + off) = make_uint4(lp[0], lp[1], lp[2], lp[3]);
        }
        __syncthreads();

        if (jt < qt) { load_v_stage(jt + 1); CP_COMMIT(); }

        // ---- O += P . V  (3-pass split) ----
        #pragma unroll
        for (int kc = 0; kc < 4; kc++) {
            uint32_t ah[4], al[4];
            split2(s[2 * kc][0],     s[2 * kc][1],     ah[0], al[0]);
            split2(s[2 * kc][2],     s[2 * kc][3],     ah[1], al[1]);
            split2(s[2 * kc + 1][0], s[2 * kc + 1][1], ah[2], al[2]);
            split2(s[2 * kc + 1][2], s[2 * kc + 1][3], ah[3], al[3]);
            #pragma unroll
            for (int dj2 = 0; dj2 < 4; dj2++) {
                int mm = lane >> 3, j = lane & 7;
                int row = kc * 16 + (mm & 1) * 8 + j;
                int chunk = 2 * dj2 + (mm >> 1);
                uint32_t off = row * 128 + ((chunk ^ (row & 7)) << 4);
                uint32_t bh4[4], bl4[4];
                ldsm_x4_t(VH + off, bh4);
                ldsm_x4_t(VL + off, bl4);
                mma16816(o[2 * dj2],     ah, &bh4[0]);
                mma16816(o[2 * dj2 + 1], ah, &bh4[2]);
                mma16816(o[2 * dj2],     al, &bh4[0]);
                mma16816(o[2 * dj2 + 1], al, &bh4[2]);
                mma16816(o[2 * dj2],     ah, &bl4[0]);
                mma16816(o[2 * dj2 + 1], ah, &bl4[2]);
            }
        }
    }

    // ---- normalize + store split-bf16 (hi,lo,hi) rows of A3 [M][3072] ----
    const int b_ = bh >> 4;
    const int h  = bh & 15;
    const float inv0 = 1.f / li0, inv1 = 1.f / li1;
    const int t0 = qbase + w * 16 + (lane >> 2);
    const int cb = h * HDIM + 2 * (lane & 3);
    const size_t m0 = (size_t)b_ * SEQ + t0;
    #pragma unroll
    for (int dj = 0; dj < 8; dj++) {
        int col = cb + dj * 8;
        uint32_t hp, lp;
        split2(o[dj][0] * inv0, o[dj][1] * inv0, hp, lp);
        __nv_bfloat16* p0 = Yd + m0 * K3 + col;
        *reinterpret_cast<uint32_t*>(p0)        = hp;
        *reinterpret_cast<uint32_t*>(p0 + 1024) = lp;
        *reinterpret_cast<uint32_t*>(p0 + 2048) = hp;
        split2(o[dj][2] * inv1, o[dj][3] * inv1, hp, lp);
        __nv_bfloat16* p1 = Yd + (m0 + 8) * K3 + col;
        *reinterpret_cast<uint32_t*>(p1)        = hp;
        *reinterpret_cast<uint32_t*>(p1 + 1024) = lp;
        *reinterpret_cast<uint32_t*>(p1 + 2048) = hp;
    }
}

// ---------------------------------------------------------------------------
// Launch graph
// d_in: x, Wq, bq, Wk, bk, Wv, bv, Wp, bp
// d_out: [ y | present_k | present_v ]
// ---------------------------------------------------------------------------
extern "C" void kernel_launch(void* const* d_in, const int* in_sizes, int n_in,
                              void* d_out, int out_size)
{
    const float* x  = (const float*)d_in[0];
    const float* Wq = (const float*)d_in[1];
    const float* bq = (const float*)d_in[2];
    const float* Wk = (const float*)d_in[3];
    const float* bk = (const float*)d_in[4];
    const float* Wv = (const float*)d_in[5];
    const float* bv = (const float*)d_in[6];
    const float* Wp = (const float*)d_in[7];
    const float* bp = (const float*)d_in[8];

    float* out  = (float*)d_out;
    float* kout = out + Y_ELEMS;
    float* vout = out + Y_ELEMS + KV_ELEMS;

    __nv_bfloat16 *a3 = nullptr, *w3 = nullptr, *q3 = nullptr, *k3 = nullptr;
    cudaGetSymbolAddress((void**)&a3, g_a3);
    cudaGetSymbolAddress((void**)&w3, g_w3);
    cudaGetSymbolAddress((void**)&q3, g_q3);
    cudaGetSymbolAddress((void**)&k3, g_k3);

    cudaFuncSetAttribute(gemm_bf16_kernel,
                         cudaFuncAttributeMaxDynamicSharedMemorySize, GSM_TOTAL);
    cudaFuncSetAttribute(attn_kernel,
                         cudaFuncAttributeMaxDynamicSharedMemorySize, ATTN_SMEM);

    const size_t wstride = (size_t)CDIM * K3;
    {
        int total2 = CDIM * 512;
        int blocks = (total2 + 255) / 256;
        conv_split_kernel<<<blocks, 256>>>(Wq, w3 + 0 * wstride, total2, 0);
        conv_split_kernel<<<blocks, 256>>>(Wk, w3 + 1 * wstride, total2, 0);
        conv_split_kernel<<<blocks, 256>>>(Wv, w3 + 2 * wstride, total2, 0);
        conv_split_kernel<<<blocks, 256>>>(Wp, w3 + 3 * wstride, total2, 0);
    }
    {
        int total2 = MROWS * 512;
        conv_split_kernel<<<(total2 + 255) / 256, 256>>>(x, a3, total2, 1);
    }

    // Fused QKV GEMM: N = 3072 over contiguous Wq|Wk|Wv
    gemm_bf16_kernel<<<dim3(24, MROWS / 128), 256, GSM_TOTAL>>>(
        a3, w3, bq, bk, bv, kout, vout, q3, k3, 1);

    // Attention: writes split-bf16 y rows directly into a3
    attn_kernel<<<dim3(SEQ / 64, BATCH * NHEAD), 128, ATTN_SMEM>>>(q3, k3, vout, a3);

    // Output projection (mode 0: only b0/out0 used)
    gemm_bf16_kernel<<<dim3(8, MROWS / 128), 256, GSM_TOTAL>>>(
        a3, w3 + 3 * wstride, bp, nullptr, nullptr,
        out, nullptr, nullptr, nullptr, 0);
}

// round 9
// speedup vs baseline: 3.4136x; 1.0140x over previous
#include <cuda_runtime.h>
#include <cuda_bf16.h>
#include <cstdint>

// Problem constants (fixed by setup_inputs)
#define BATCH 4
#define SEQ   2048
#define CDIM  1024
#define NHEAD 16
#define HDIM  64
#define MROWS (BATCH * SEQ)          // 8192
#define K3    3072                   // split-bf16 tripled K (projections)
#define D3    192                    // split-bf16 tripled head dim (attention)
#define Y_ELEMS ((size_t)MROWS * CDIM)                  // 8,388,608
#define KV_ELEMS ((size_t)BATCH * NHEAD * SEQ * HDIM)   // 8,388,608

// exp2-folded softmax scale: S2 = (0.125 * log2 e) * (q.k)
#define QSCALE 0.18033688011112042f

// ---------------------------------------------------------------------------
// Device scratch (allocation-free per harness rules)
// ---------------------------------------------------------------------------
__device__ __align__(256) __nv_bfloat16 g_a3[(size_t)MROWS * K3];    // A-side split (x, then y)
__device__ __align__(256) __nv_bfloat16 g_w3[4][(size_t)CDIM * K3];  // Wq,Wk,Wv,Wp split (contiguous)
__device__ __align__(256) __nv_bfloat16 g_q3[(size_t)KV_ELEMS * 3];  // Q split [B,H,T,192]
__device__ __align__(256) __nv_bfloat16 g_k3[(size_t)KV_ELEMS * 3];  // K split [B,H,T,192]

// ---------------------------------------------------------------------------
// PTX helpers (base-target safe: cp.async / ldmatrix / mma.sync only)
// ---------------------------------------------------------------------------
__device__ __forceinline__ uint32_t smem_to_u32(const void* p) {
    uint32_t a;
    asm("{ .reg .u64 t; cvta.to.shared.u64 t, %1; cvt.u32.u64 %0, t; }" : "=r"(a) : "l"(p));
    return a;
}

#define CP_ASYNC16(dst, src) \
    asm volatile("cp.async.cg.shared.global [%0], [%1], 16;" :: "r"(dst), "l"(src))
#define CP_COMMIT() asm volatile("cp.async.commit_group;" ::: "memory")
#define CP_WAIT1()  asm volatile("cp.async.wait_group 1;" ::: "memory")
#define CP_WAIT0()  asm volatile("cp.async.wait_group 0;" ::: "memory")

__device__ __forceinline__ void ldsm_x4(uint32_t addr, uint32_t* r) {
    asm volatile("ldmatrix.sync.aligned.m8n8.x4.shared.b16 {%0,%1,%2,%3}, [%4];"
                 : "=r"(r[0]), "=r"(r[1]), "=r"(r[2]), "=r"(r[3]) : "r"(addr));
}
__device__ __forceinline__ void ldsm_x4_t(uint32_t addr, uint32_t* r) {
    asm volatile("ldmatrix.sync.aligned.m8n8.x4.trans.shared.b16 {%0,%1,%2,%3}, [%4];"
                 : "=r"(r[0]), "=r"(r[1]), "=r"(r[2]), "=r"(r[3]) : "r"(addr));
}

__device__ __forceinline__ void mma16816(float* c, const uint32_t* a, const uint32_t* b) {
    asm volatile(
        "mma.sync.aligned.m16n8k16.row.col.f32.bf16.bf16.f32 "
        "{%0,%1,%2,%3}, {%4,%5,%6,%7}, {%8,%9}, {%0,%1,%2,%3};"
        : "+f"(c[0]), "+f"(c[1]), "+f"(c[2]), "+f"(c[3])
        : "r"(a[0]), "r"(a[1]), "r"(a[2]), "r"(a[3]), "r"(b[0]), "r"(b[1]));
}

// Split two fp32 into packed bf16 hi-pair / lo-pair (elem0 in low half).
__device__ __forceinline__ void split2(float x0, float x1, uint32_t& hp, uint32_t& lp) {
    __nv_bfloat16 h0 = __float2bfloat16(x0);
    __nv_bfloat16 h1 = __float2bfloat16(x1);
    float r0 = x0 - __bfloat162float(h0);
    float r1 = x1 - __bfloat162float(h1);
    __nv_bfloat162 hh(h0, h1);
    __nv_bfloat162 ll(__float2bfloat16(r0), __float2bfloat16(r1));
    hp = *reinterpret_cast<uint32_t*>(&hh);
    lp = *reinterpret_cast<uint32_t*>(&ll);
}

// ---------------------------------------------------------------------------
// Split-bf16 conversion: src [rows][1024] fp32 -> dst [rows][3072] bf16.
// modeA=1: blocks (hi, lo, hi) ; modeA=0: blocks (hi, hi, lo)
// ---------------------------------------------------------------------------
__global__ __launch_bounds__(256) void conv_split_kernel(
    const float* __restrict__ src, __nv_bfloat16* __restrict__ dst,
    int total2, int modeA)
{
    int i = blockIdx.x * blockDim.x + threadIdx.x;
    if (i >= total2) return;
    int r = i >> 9;
    int c = (i & 511) << 1;
    float2 v = reinterpret_cast<const float2*>(src)[i];
    uint32_t hp, lp;
    split2(v.x, v.y, hp, lp);
    uint32_t* base = reinterpret_cast<uint32_t*>(dst + (size_t)r * K3 + c);
    base[0]    = hp;
    base[512]  = modeA ? lp : hp;
    base[1024] = modeA ? hp : lp;
}

// ---------------------------------------------------------------------------
// mma.sync split-bf16 GEMM: out = A3 @ W3^T + bias, 3-stage cp.async pipeline.
// (unchanged from R8 — validated)
// ---------------------------------------------------------------------------
#define GSM_TOTAL 98304   // 3 stages x (16KB A + 16KB B)

__global__ __launch_bounds__(256) void gemm_bf16_kernel(
    const __nv_bfloat16* __restrict__ A3, const __nv_bfloat16* __restrict__ W3,
    const float* __restrict__ b0, const float* __restrict__ b1,
    const float* __restrict__ b2,
    float* __restrict__ out0, float* __restrict__ out1,
    __nv_bfloat16* __restrict__ q3, __nv_bfloat16* __restrict__ k3,
    int mode)
{
    extern __shared__ char smem[];
    const uint32_t sA = smem_to_u32(smem);      // 3 x 16KB
    const uint32_t sB = sA + 49152;             // 3 x 16KB

    const int tid  = threadIdx.x;
    const int wid  = tid >> 5;
    const int lane = tid & 31;
    const int wm = wid >> 1;
    const int wn = wid & 1;
    const int mbase = blockIdx.y * 128;
    const int nbase = blockIdx.x * 128;

    const __nv_bfloat16* Ag = A3 + (size_t)mbase * K3;
    const __nv_bfloat16* Bg = W3 + (size_t)nbase * K3;

    float acc[2][8][4];
    #pragma unroll
    for (int i = 0; i < 2; i++)
        #pragma unroll
        for (int j = 0; j < 8; j++)
            #pragma unroll
            for (int q = 0; q < 4; q++) acc[i][j][q] = 0.f;

    const int lr  = tid & 7;
    const int lc  = (tid >> 3) & 7;
    const int lb0 = tid >> 6;

    const int NITER = K3 / 64;     // 48

    auto load_chunk = [&](int it, int slot) {
        const size_t kofs = (size_t)it * 64;
        const uint32_t aBase = sA + slot * 16384;
        const uint32_t bBase = sB + slot * 16384;
        #pragma unroll
        for (int t = 0; t < 4; t++) {
            int row = (lb0 + t * 4) * 8 + lr;
            uint32_t doff = row * 128 + ((lc ^ lr) << 4);
            const __nv_bfloat16* asrc = Ag + (size_t)row * K3 + kofs + lc * 8;
            const __nv_bfloat16* bsrc = Bg + (size_t)row * K3 + kofs + lc * 8;
            CP_ASYNC16(aBase + doff, asrc);
            CP_ASYNC16(bBase + doff, bsrc);
        }
    };

    load_chunk(0, 0); CP_COMMIT();
    load_chunk(1, 1); CP_COMMIT();

    int slot = 0;
    for (int it = 0; it < NITER; ++it) {
        CP_WAIT1();
        __syncthreads();
        int nslot = slot + 2; if (nslot >= 3) nslot -= 3;
        if (it + 2 < NITER) load_chunk(it + 2, nslot);
        CP_COMMIT();

        const uint32_t aBase = sA + slot * 16384;
        const uint32_t bBase = sB + slot * 16384;

        #pragma unroll
        for (int ks = 0; ks < 4; ks++) {
            uint32_t af[2][4];
            #pragma unroll
            for (int mi = 0; mi < 2; mi++) {
                int row = wm * 32 + mi * 16 + (lane & 15);
                int chunk = 2 * ks + (lane >> 4);
                uint32_t addr = aBase + row * 128 + ((chunk ^ (row & 7)) << 4);
                ldsm_x4(addr, af[mi]);
            }
            uint32_t bf[8][2];
            #pragma unroll
            for (int ni = 0; ni < 4; ni++) {
                int row = wn * 64 + ni * 16 + ((lane >> 4) << 3) + (lane & 7);
                int chunk = 2 * ks + ((lane >> 3) & 1);
                uint32_t addr = bBase + row * 128 + ((chunk ^ (row & 7)) << 4);
                uint32_t r4[4];
                ldsm_x4(addr, r4);
                bf[2 * ni][0]     = r4[0];
                bf[2 * ni][1]     = r4[1];
                bf[2 * ni + 1][0] = r4[2];
                bf[2 * ni + 1][1] = r4[3];
            }
            #pragma unroll
            for (int mi = 0; mi < 2; mi++)
                #pragma unroll
                for (int nj = 0; nj < 8; nj++)
                    mma16816(acc[mi][nj], af[mi], bf[nj]);
        }
        if (++slot >= 3) slot = 0;
    }

    // ---- epilogue ----
    const int which = nbase >> 10;
    const float* bias = (mode == 0) ? b0 : (which == 0 ? b0 : (which == 1 ? b1 : b2));
    const int qr = lane >> 2;
    const int qc = (lane & 3) * 2;
    #pragma unroll
    for (int mi = 0; mi < 2; mi++) {
        #pragma unroll
        for (int half = 0; half < 2; half++) {
            int m = mbase + wm * 32 + mi * 16 + qr + half * 8;
            int b_ = m >> 11, t = m & 2047;
            #pragma unroll
            for (int nj = 0; nj < 8; nj++) {
                int ng = nbase + wn * 64 + nj * 8 + qc;
                int n  = ng & 1023;
                float vx = acc[mi][nj][half * 2 + 0] + bias[n];
                float vy = acc[mi][nj][half * 2 + 1] + bias[n + 1];
                if (mode == 0) {
                    float2 o{vx, vy};
                    *reinterpret_cast<float2*>(out0 + (size_t)m * CDIM + n) = o;
                } else {
                    int h = n >> 6, d = n & 63;
                    size_t bht = ((size_t)(b_ * NHEAD + h)) * SEQ + t;
                    if (which == 0) {
                        vx *= QSCALE; vy *= QSCALE;
                        uint32_t hp, lp;
                        split2(vx, vy, hp, lp);
                        size_t base2 = bht * D3 + d;
                        *reinterpret_cast<uint32_t*>(q3 + base2)       = hp;
                        *reinterpret_cast<uint32_t*>(q3 + base2 + 64)  = lp;
                        *reinterpret_cast<uint32_t*>(q3 + base2 + 128) = hp;
                    } else if (which == 1) {
                        float2 o{vx, vy};
                        *reinterpret_cast<float2*>(out0 + bht * HDIM + d) = o;
                        uint32_t hp, lp;
                        split2(vx, vy, hp, lp);
                        size_t base2 = bht * D3 + d;
                        *reinterpret_cast<uint32_t*>(k3 + base2)       = hp;
                        *reinterpret_cast<uint32_t*>(k3 + base2 + 64)  = hp;
                        *reinterpret_cast<uint32_t*>(k3 + base2 + 128) = lp;
                    } else {
                        float2 o{vx, vy};
                        *reinterpret_cast<float2*>(out1 + bht * HDIM + d) = o;
                    }
                }
            }
        }
    }
}

// ---------------------------------------------------------------------------
// HMMA causal flash attention, BM=128 / BN=64, 256 threads (8 warps x 16 rows).
// Q3: [B,H,T,192] bf16 split (scaled), K3: [B,H,T,192] bf16 split, V fp32 [B,H,T,64].
// Output: split-bf16 (hi,lo,hi) rows of A3 [M][3072] for the proj GEMM.
// smem: Qs 48K | Ks 2x24K | Vstage 16K | Vh 8K | Vl 8K = 128K
// ---------------------------------------------------------------------------
#define QS_OFF   0
#define KS_OFF   49152
#define VST_OFF  98304
#define VH_OFF   114688
#define VL_OFF   122880
#define ATTN_SMEM 131072

__global__ __launch_bounds__(256) void attn_kernel(
    const __nv_bfloat16* __restrict__ Q3, const __nv_bfloat16* __restrict__ K3g,
    const float* __restrict__ V, __nv_bfloat16* __restrict__ Yd)
{
    extern __shared__ char smem[];
    const uint32_t sm = smem_to_u32(smem);
    const uint32_t QS = sm + QS_OFF;
    const uint32_t KS = sm + KS_OFF;
    const uint32_t VST = sm + VST_OFF;
    const uint32_t VH = sm + VH_OFF;
    const uint32_t VL = sm + VL_OFF;

    const int tid = threadIdx.x;
    const int w = tid >> 5;                         // 0..7
    const int lane = tid & 31;
    const int qt = (int)gridDim.x - 1 - (int)blockIdx.x;  // long CTAs first
    const int bh = blockIdx.y;                      // 0..63
    const int qbase = qt * 128;

    const __nv_bfloat16* Qg = Q3 + ((size_t)bh * SEQ + qbase) * D3;
    const __nv_bfloat16* Kg = K3g + (size_t)bh * SEQ * D3;
    const float* Vg = V + (size_t)bh * SEQ * HDIM;

    // ---- loaders (256 threads) ----
    auto load_q = [&]() {
        #pragma unroll
        for (int i = 0; i < 12; i++) {
            int g = tid + i * 256;          // 0..3071
            int r = g & 127, bc = g >> 7;   // bc 0..23
            int b = bc >> 3, c = bc & 7;
            const __nv_bfloat16* src = Qg + (size_t)r * D3 + b * 64 + c * 8;
            uint32_t dst = QS + b * 16384 + r * 128 + ((c ^ (r & 7)) << 4);
            CP_ASYNC16(dst, src);
        }
    };
    auto load_k = [&](int jt, int buf) {
        const __nv_bfloat16* base = Kg + (size_t)jt * 64 * D3;
        uint32_t kb = KS + buf * 24576;
        #pragma unroll
        for (int i = 0; i < 6; i++) {
            int g = tid + i * 256;          // 0..1535
            int r = g & 63, bc = g >> 6;    // bc 0..23
            int b = bc >> 3, c = bc & 7;
            const __nv_bfloat16* src = base + (size_t)r * D3 + b * 64 + c * 8;
            uint32_t dst = kb + b * 8192 + r * 128 + ((c ^ (r & 7)) << 4);
            CP_ASYNC16(dst, src);
        }
    };
    auto load_v_stage = [&](int jt) {
        const float* base = Vg + (size_t)jt * 64 * HDIM;
        #pragma unroll
        for (int i = 0; i < 4; i++) {
            int g = tid + i * 256;          // 0..1023
            int r = g >> 4, c = g & 15;
            CP_ASYNC16(VST + r * 256 + c * 16, base + (size_t)r * HDIM + c * 4);
        }
    };

    load_q();
    load_k(0, 0);
    load_v_stage(0);
    CP_COMMIT();

    float o[8][4];
    #pragma unroll
    for (int j = 0; j < 8; j++)
        #pragma unroll
        for (int q = 0; q < 4; q++) o[j][q] = 0.f;
    float mi0 = -1e30f, mi1 = -1e30f, li0 = 0.f, li1 = 0.f;

    const int jmax = 2 * qt + 1;
    for (int jt = 0; jt <= jmax; ++jt) {
        const int buf = jt & 1;
        if (jt < jmax) { load_k(jt + 1, buf ^ 1); CP_COMMIT(); CP_WAIT1(); }
        else           { CP_WAIT0(); }
        __syncthreads();

        // ---- S = Q . K^T over 192 split dims ----
        float s[8][4];
        #pragma unroll
        for (int j = 0; j < 8; j++)
            #pragma unroll
            for (int q = 0; q < 4; q++) s[j][q] = 0.f;

        const uint32_t kb = KS + buf * 24576;
        #pragma unroll
        for (int b = 0; b < 3; b++) {
            #pragma unroll
            for (int ks = 0; ks < 4; ks++) {
                uint32_t af[4];
                {
                    int row = w * 16 + (lane & 15);
                    int chunk = 2 * ks + (lane >> 4);
                    ldsm_x4(QS + b * 16384 + row * 128 + ((chunk ^ (row & 7)) << 4), af);
                }
                uint32_t bf[8][2];
                #pragma unroll
                for (int ni = 0; ni < 4; ni++) {
                    int row = ni * 16 + ((lane >> 4) << 3) + (lane & 7);
                    int chunk = 2 * ks + ((lane >> 3) & 1);
                    uint32_t r4[4];
                    ldsm_x4(kb + b * 8192 + row * 128 + ((chunk ^ (row & 7)) << 4), r4);
                    bf[2 * ni][0] = r4[0]; bf[2 * ni][1] = r4[1];
                    bf[2 * ni + 1][0] = r4[2]; bf[2 * ni + 1][1] = r4[3];
                }
                #pragma unroll
                for (int nj = 0; nj < 8; nj++)
                    mma16816(s[nj], af, bf[nj]);
            }
        }

        // ---- causal mask (only where the k-tile can cross the diagonal) ----
        if (jt * 64 + 63 > qbase + w * 16) {
            const int gr = qbase + w * 16 + (lane >> 2);   // global q row (first half)
            const int cb = jt * 64 + 2 * (lane & 3);
            #pragma unroll
            for (int nj = 0; nj < 8; nj++) {
                int c0 = cb + nj * 8;
                if (c0 > gr)     s[nj][0] = -1e30f;
                if (c0 + 1 > gr) s[nj][1] = -1e30f;
                if (c0 > gr + 8)     s[nj][2] = -1e30f;
                if (c0 + 1 > gr + 8) s[nj][3] = -1e30f;
            }
        }

        // ---- online softmax (base-2; scale folded into Q) ----
        float mx0 = -1e30f, mx1 = -1e30f;
        #pragma unroll
        for (int nj = 0; nj < 8; nj++) {
            mx0 = fmaxf(mx0, fmaxf(s[nj][0], s[nj][1]));
            mx1 = fmaxf(mx1, fmaxf(s[nj][2], s[nj][3]));
        }
        mx0 = fmaxf(mx0, __shfl_xor_sync(0xffffffffu, mx0, 1));
        mx0 = fmaxf(mx0, __shfl_xor_sync(0xffffffffu, mx0, 2));
        mx1 = fmaxf(mx1, __shfl_xor_sync(0xffffffffu, mx1, 1));
        mx1 = fmaxf(mx1, __shfl_xor_sync(0xffffffffu, mx1, 2));
        float mn0 = fmaxf(mi0, mx0), mn1 = fmaxf(mi1, mx1);
        float c0 = exp2f(mi0 - mn0), c1 = exp2f(mi1 - mn1);
        mi0 = mn0; mi1 = mn1;
        float rs0 = 0.f, rs1 = 0.f;
        #pragma unroll
        for (int nj = 0; nj < 8; nj++) {
            s[nj][0] = exp2f(s[nj][0] - mn0); rs0 += s[nj][0];
            s[nj][1] = exp2f(s[nj][1] - mn0); rs0 += s[nj][1];
            s[nj][2] = exp2f(s[nj][2] - mn1); rs1 += s[nj][2];
            s[nj][3] = exp2f(s[nj][3] - mn1); rs1 += s[nj][3];
        }
        rs0 += __shfl_xor_sync(0xffffffffu, rs0, 1);
        rs0 += __shfl_xor_sync(0xffffffffu, rs0, 2);
        rs1 += __shfl_xor_sync(0xffffffffu, rs1, 1);
        rs1 += __shfl_xor_sync(0xffffffffu, rs1, 2);
        li0 = li0 * c0 + rs0;
        li1 = li1 * c1 + rs1;
        #pragma unroll
        for (int dj = 0; dj < 8; dj++) {
            o[dj][0] *= c0; o[dj][1] *= c0;
            o[dj][2] *= c1; o[dj][3] *= c1;
        }

        // ---- convert V stage (fp32) -> Vh/Vl bf16 tiles ----
        #pragma unroll
        for (int i = 0; i < 2; i++) {
            int g = tid + i * 256;          // 0..511
            int r = g >> 3, c = g & 7;
            const float* sp = reinterpret_cast<const float*>(smem + VST_OFF) + r * 64 + c * 8;
            uint32_t hp[4], lp[4];
            #pragma unroll
            for (int e = 0; e < 4; e++)
                split2(sp[2 * e], sp[2 * e + 1], hp[e], lp[e]);
            uint32_t off = r * 128 + ((c ^ (r & 7)) << 4);
            *reinterpret_cast<uint4*>(smem + VH_OFF + off) = make_uint4(hp[0], hp[1], hp[2], hp[3]);
            *reinterpret_cast<uint4*>(smem + VL_OFF + off) = make_uint4(lp[0], lp[1], lp[2], lp[3]);
        }
        __syncthreads();

        if (jt < jmax) { load_v_stage(jt + 1); CP_COMMIT(); }

        // ---- O += P . V  (3-pass split) ----
        #pragma unroll
        for (int kc = 0; kc < 4; kc++) {
            uint32_t ah[4], al[4];
            split2(s[2 * kc][0],     s[2 * kc][1],     ah[0], al[0]);
            split2(s[2 * kc][2],     s[2 * kc][3],     ah[1], al[1]);
            split2(s[2 * kc + 1][0], s[2 * kc + 1][1], ah[2], al[2]);
            split2(s[2 * kc + 1][2], s[2 * kc + 1][3], ah[3], al[3]);
            #pragma unroll
            for (int dj2 = 0; dj2 < 4; dj2++) {
                int mm = lane >> 3, j = lane & 7;
                int row = kc * 16 + (mm & 1) * 8 + j;
                int chunk = 2 * dj2 + (mm >> 1);
                uint32_t off = row * 128 + ((chunk ^ (row & 7)) << 4);
                uint32_t bh4[4], bl4[4];
                ldsm_x4_t(VH + off, bh4);
                ldsm_x4_t(VL + off, bl4);
                mma16816(o[2 * dj2],     ah, &bh4[0]);
                mma16816(o[2 * dj2 + 1], ah, &bh4[2]);
                mma16816(o[2 * dj2],     al, &bh4[0]);
                mma16816(o[2 * dj2 + 1], al, &bh4[2]);
                mma16816(o[2 * dj2],     ah, &bl4[0]);
                mma16816(o[2 * dj2 + 1], ah, &bl4[2]);
            }
        }
    }

    // ---- normalize + store split-bf16 (hi,lo,hi) rows of A3 [M][3072] ----
    const int b_ = bh >> 4;
    const int h  = bh & 15;
    const float inv0 = 1.f / li0, inv1 = 1.f / li1;
    const int t0 = qbase + w * 16 + (lane >> 2);
    const int cb = h * HDIM + 2 * (lane & 3);
    const size_t m0 = (size_t)b_ * SEQ + t0;
    #pragma unroll
    for (int dj = 0; dj < 8; dj++) {
        int col = cb + dj * 8;
        uint32_t hp, lp;
        split2(o[dj][0] * inv0, o[dj][1] * inv0, hp, lp);
        __nv_bfloat16* p0 = Yd + m0 * K3 + col;
        *reinterpret_cast<uint32_t*>(p0)        = hp;
        *reinterpret_cast<uint32_t*>(p0 + 1024) = lp;
        *reinterpret_cast<uint32_t*>(p0 + 2048) = hp;
        split2(o[dj][2] * inv1, o[dj][3] * inv1, hp, lp);
        __nv_bfloat16* p1 = Yd + (m0 + 8) * K3 + col;
        *reinterpret_cast<uint32_t*>(p1)        = hp;
        *reinterpret_cast<uint32_t*>(p1 + 1024) = lp;
        *reinterpret_cast<uint32_t*>(p1 + 2048) = hp;
    }
}

// ---------------------------------------------------------------------------
// Launch graph
// d_in: x, Wq, bq, Wk, bk, Wv, bv, Wp, bp
// d_out: [ y | present_k | present_v ]
// ---------------------------------------------------------------------------
extern "C" void kernel_launch(void* const* d_in, const int* in_sizes, int n_in,
                              void* d_out, int out_size)
{
    const float* x  = (const float*)d_in[0];
    const float* Wq = (const float*)d_in[1];
    const float* bq = (const float*)d_in[2];
    const float* Wk = (const float*)d_in[3];
    const float* bk = (const float*)d_in[4];
    const float* Wv = (const float*)d_in[5];
    const float* bv = (const float*)d_in[6];
    const float* Wp = (const float*)d_in[7];
    const float* bp = (const float*)d_in[8];

    float* out  = (float*)d_out;
    float* kout = out + Y_ELEMS;
    float* vout = out + Y_ELEMS + KV_ELEMS;

    __nv_bfloat16 *a3 = nullptr, *w3 = nullptr, *q3 = nullptr, *k3 = nullptr;
    cudaGetSymbolAddress((void**)&a3, g_a3);
    cudaGetSymbolAddress((void**)&w3, g_w3);
    cudaGetSymbolAddress((void**)&q3, g_q3);
    cudaGetSymbolAddress((void**)&k3, g_k3);

    cudaFuncSetAttribute(gemm_bf16_kernel,
                         cudaFuncAttributeMaxDynamicSharedMemorySize, GSM_TOTAL);
    cudaFuncSetAttribute(attn_kernel,
                         cudaFuncAttributeMaxDynamicSharedMemorySize, ATTN_SMEM);

    const size_t wstride = (size_t)CDIM * K3;
    {
        int total2 = CDIM * 512;
        int blocks = (total2 + 255) / 256;
        conv_split_kernel<<<blocks, 256>>>(Wq, w3 + 0 * wstride, total2, 0);
        conv_split_kernel<<<blocks, 256>>>(Wk, w3 + 1 * wstride, total2, 0);
        conv_split_kernel<<<blocks, 256>>>(Wv, w3 + 2 * wstride, total2, 0);
        conv_split_kernel<<<blocks, 256>>>(Wp, w3 + 3 * wstride, total2, 0);
    }
    {
        int total2 = MROWS * 512;
        conv_split_kernel<<<(total2 + 255) / 256, 256>>>(x, a3, total2, 1);
    }

    // Fused QKV GEMM: N = 3072 over contiguous Wq|Wk|Wv
    gemm_bf16_kernel<<<dim3(24, MROWS / 128), 256, GSM_TOTAL>>>(
        a3, w3, bq, bk, bv, kout, vout, q3, k3, 1);

    // Attention (BM=128): writes split-bf16 y rows directly into a3
    attn_kernel<<<dim3(SEQ / 128, BATCH * NHEAD), 256, ATTN_SMEM>>>(q3, k3, vout, a3);

    // Output projection (mode 0: only b0/out0 used)
    gemm_bf16_kernel<<<dim3(8, MROWS / 128), 256, GSM_TOTAL>>>(
        a3, w3 + 3 * wstride, bp, nullptr, nullptr,
        out, nullptr, nullptr, nullptr, 0);
}

// round 10
// speedup vs baseline: 3.5502x; 1.0400x over previous
#include <cuda_runtime.h>
#include <cuda_bf16.h>
#include <cstdint>

// Problem constants (fixed by setup_inputs)
#define BATCH 4
#define SEQ   2048
#define CDIM  1024
#define NHEAD 16
#define HDIM  64
#define MROWS (BATCH * SEQ)          // 8192
#define K3    3072                   // split-bf16 tripled K (projections)
#define D3    192                    // split-bf16 tripled head dim (attention)
#define Y_ELEMS ((size_t)MROWS * CDIM)                  // 8,388,608
#define KV_ELEMS ((size_t)BATCH * NHEAD * SEQ * HDIM)   // 8,388,608

// exp2-folded softmax scale: S2 = (0.125 * log2 e) * (q.k)
#define QSCALE 0.18033688011112042f

// ---------------------------------------------------------------------------
// Device scratch (allocation-free per harness rules)
// ---------------------------------------------------------------------------
__device__ __align__(256) __nv_bfloat16 g_a3[(size_t)MROWS * K3];    // A-side split (x, then y)
__device__ __align__(256) __nv_bfloat16 g_w3[4][(size_t)CDIM * K3];  // Wq,Wk,Wv,Wp split (contiguous)
__device__ __align__(256) __nv_bfloat16 g_q3[(size_t)KV_ELEMS * 3];  // Q split [B,H,T,192]
__device__ __align__(256) __nv_bfloat16 g_k3[(size_t)KV_ELEMS * 3];  // K split [B,H,T,192]
__device__ __align__(256) __nv_bfloat16 g_v2[(size_t)KV_ELEMS * 2];  // V split [B,H,T,(hi64|lo64)]

// ---------------------------------------------------------------------------
// PTX helpers (base-target safe: cp.async / ldmatrix / mma.sync only)
// ---------------------------------------------------------------------------
__device__ __forceinline__ uint32_t smem_to_u32(const void* p) {
    uint32_t a;
    asm("{ .reg .u64 t; cvta.to.shared.u64 t, %1; cvt.u32.u64 %0, t; }" : "=r"(a) : "l"(p));
    return a;
}

#define CP_ASYNC16(dst, src) \
    asm volatile("cp.async.cg.shared.global [%0], [%1], 16;" :: "r"(dst), "l"(src))
#define CP_COMMIT() asm volatile("cp.async.commit_group;" ::: "memory")
#define CP_WAIT1()  asm volatile("cp.async.wait_group 1;" ::: "memory")
#define CP_WAIT0()  asm volatile("cp.async.wait_group 0;" ::: "memory")

__device__ __forceinline__ void ldsm_x4(uint32_t addr, uint32_t* r) {
    asm volatile("ldmatrix.sync.aligned.m8n8.x4.shared.b16 {%0,%1,%2,%3}, [%4];"
                 : "=r"(r[0]), "=r"(r[1]), "=r"(r[2]), "=r"(r[3]) : "r"(addr));
}
__device__ __forceinline__ void ldsm_x4_t(uint32_t addr, uint32_t* r) {
    asm volatile("ldmatrix.sync.aligned.m8n8.x4.trans.shared.b16 {%0,%1,%2,%3}, [%4];"
                 : "=r"(r[0]), "=r"(r[1]), "=r"(r[2]), "=r"(r[3]) : "r"(addr));
}

__device__ __forceinline__ void mma16816(float* c, const uint32_t* a, const uint32_t* b) {
    asm volatile(
        "mma.sync.aligned.m16n8k16.row.col.f32.bf16.bf16.f32 "
        "{%0,%1,%2,%3}, {%4,%5,%6,%7}, {%8,%9}, {%0,%1,%2,%3};"
        : "+f"(c[0]), "+f"(c[1]), "+f"(c[2]), "+f"(c[3])
        : "r"(a[0]), "r"(a[1]), "r"(a[2]), "r"(a[3]), "r"(b[0]), "r"(b[1]));
}

// Split two fp32 into packed bf16 hi-pair / lo-pair (elem0 in low half).
__device__ __forceinline__ void split2(float x0, float x1, uint32_t& hp, uint32_t& lp) {
    __nv_bfloat16 h0 = __float2bfloat16(x0);
    __nv_bfloat16 h1 = __float2bfloat16(x1);
    float r0 = x0 - __bfloat162float(h0);
    float r1 = x1 - __bfloat162float(h1);
    __nv_bfloat162 hh(h0, h1);
    __nv_bfloat162 ll(__float2bfloat16(r0), __float2bfloat16(r1));
    hp = *reinterpret_cast<uint32_t*>(&hh);
    lp = *reinterpret_cast<uint32_t*>(&ll);
}

// ---------------------------------------------------------------------------
// Split-bf16 conversion: src [rows][1024] fp32 -> dst [rows][3072] bf16.
// modeA=1: blocks (hi, lo, hi) ; modeA=0: blocks (hi, hi, lo)
// ---------------------------------------------------------------------------
__global__ __launch_bounds__(256) void conv_split_kernel(
    const float* __restrict__ src, __nv_bfloat16* __restrict__ dst,
    int total2, int modeA)
{
    int i = blockIdx.x * blockDim.x + threadIdx.x;
    if (i >= total2) return;
    int r = i >> 9;
    int c = (i & 511) << 1;
    float2 v = reinterpret_cast<const float2*>(src)[i];
    uint32_t hp, lp;
    split2(v.x, v.y, hp, lp);
    uint32_t* base = reinterpret_cast<uint32_t*>(dst + (size_t)r * K3 + c);
    base[0]    = hp;
    base[512]  = modeA ? lp : hp;
    base[1024] = modeA ? hp : lp;
}

// ---------------------------------------------------------------------------
// mma.sync split-bf16 GEMM: out = A3 @ W3^T + bias, 3-stage cp.async pipeline.
// mode 0: proj -> out0 fp32 [M,1024] (grid.x = 8)
// mode 1: fused QKV over Nrows=3072 (grid.x = 24):
//   Q -> (val+bq)*QSCALE split (hi,lo,hi) into q3 [B,H,T,192]
//   K -> val+bk fp32 into out0 [B,H,T,D] + split (hi,hi,lo) into k3
//   V -> val+bv fp32 into out1 [B,H,T,D] + split (hi|lo) into v2 [B,H,T,128]
// ---------------------------------------------------------------------------
#define GSM_TOTAL 98304   // 3 stages x (16KB A + 16KB B)

__global__ __launch_bounds__(256) void gemm_bf16_kernel(
    const __nv_bfloat16* __restrict__ A3, const __nv_bfloat16* __restrict__ W3,
    const float* __restrict__ b0, const float* __restrict__ b1,
    const float* __restrict__ b2,
    float* __restrict__ out0, float* __restrict__ out1,
    __nv_bfloat16* __restrict__ q3, __nv_bfloat16* __restrict__ k3,
    __nv_bfloat16* __restrict__ v2,
    int mode)
{
    extern __shared__ char smem[];
    const uint32_t sA = smem_to_u32(smem);      // 3 x 16KB
    const uint32_t sB = sA + 49152;             // 3 x 16KB

    const int tid  = threadIdx.x;
    const int wid  = tid >> 5;
    const int lane = tid & 31;
    const int wm = wid >> 1;
    const int wn = wid & 1;
    const int mbase = blockIdx.y * 128;
    const int nbase = blockIdx.x * 128;

    const __nv_bfloat16* Ag = A3 + (size_t)mbase * K3;
    const __nv_bfloat16* Bg = W3 + (size_t)nbase * K3;

    float acc[2][8][4];
    #pragma unroll
    for (int i = 0; i < 2; i++)
        #pragma unroll
        for (int j = 0; j < 8; j++)
            #pragma unroll
            for (int q = 0; q < 4; q++) acc[i][j][q] = 0.f;

    const int lr  = tid & 7;
    const int lc  = (tid >> 3) & 7;
    const int lb0 = tid >> 6;

    const int NITER = K3 / 64;     // 48

    auto load_chunk = [&](int it, int slot) {
        const size_t kofs = (size_t)it * 64;
        const uint32_t aBase = sA + slot * 16384;
        const uint32_t bBase = sB + slot * 16384;
        #pragma unroll
        for (int t = 0; t < 4; t++) {
            int row = (lb0 + t * 4) * 8 + lr;
            uint32_t doff = row * 128 + ((lc ^ lr) << 4);
            const __nv_bfloat16* asrc = Ag + (size_t)row * K3 + kofs + lc * 8;
            const __nv_bfloat16* bsrc = Bg + (size_t)row * K3 + kofs + lc * 8;
            CP_ASYNC16(aBase + doff, asrc);
            CP_ASYNC16(bBase + doff, bsrc);
        }
    };

    load_chunk(0, 0); CP_COMMIT();
    load_chunk(1, 1); CP_COMMIT();

    int slot = 0;
    for (int it = 0; it < NITER; ++it) {
        CP_WAIT1();
        __syncthreads();
        int nslot = slot + 2; if (nslot >= 3) nslot -= 3;
        if (it + 2 < NITER) load_chunk(it + 2, nslot);
        CP_COMMIT();

        const uint32_t aBase = sA + slot * 16384;
        const uint32_t bBase = sB + slot * 16384;

        #pragma unroll
        for (int ks = 0; ks < 4; ks++) {
            uint32_t af[2][4];
            #pragma unroll
            for (int mi = 0; mi < 2; mi++) {
                int row = wm * 32 + mi * 16 + (lane & 15);
                int chunk = 2 * ks + (lane >> 4);
                uint32_t addr = aBase + row * 128 + ((chunk ^ (row & 7)) << 4);
                ldsm_x4(addr, af[mi]);
            }
            uint32_t bf[8][2];
            #pragma unroll
            for (int ni = 0; ni < 4; ni++) {
                int row = wn * 64 + ni * 16 + ((lane >> 4) << 3) + (lane & 7);
                int chunk = 2 * ks + ((lane >> 3) & 1);
                uint32_t addr = bBase + row * 128 + ((chunk ^ (row & 7)) << 4);
                uint32_t r4[4];
                ldsm_x4(addr, r4);
                bf[2 * ni][0]     = r4[0];
                bf[2 * ni][1]     = r4[1];
                bf[2 * ni + 1][0] = r4[2];
                bf[2 * ni + 1][1] = r4[3];
            }
            #pragma unroll
            for (int mi = 0; mi < 2; mi++)
                #pragma unroll
                for (int nj = 0; nj < 8; nj++)
                    mma16816(acc[mi][nj], af[mi], bf[nj]);
        }
        if (++slot >= 3) slot = 0;
    }

    // ---- epilogue ----
    const int which = nbase >> 10;
    const float* bias = (mode == 0) ? b0 : (which == 0 ? b0 : (which == 1 ? b1 : b2));
    const int qr = lane >> 2;
    const int qc = (lane & 3) * 2;
    #pragma unroll
    for (int mi = 0; mi < 2; mi++) {
        #pragma unroll
        for (int half = 0; half < 2; half++) {
            int m = mbase + wm * 32 + mi * 16 + qr + half * 8;
            int b_ = m >> 11, t = m & 2047;
            #pragma unroll
            for (int nj = 0; nj < 8; nj++) {
                int ng = nbase + wn * 64 + nj * 8 + qc;
                int n  = ng & 1023;
                float vx = acc[mi][nj][half * 2 + 0] + bias[n];
                float vy = acc[mi][nj][half * 2 + 1] + bias[n + 1];
                if (mode == 0) {
                    float2 o{vx, vy};
                    *reinterpret_cast<float2*>(out0 + (size_t)m * CDIM + n) = o;
                } else {
                    int h = n >> 6, d = n & 63;
                    size_t bht = ((size_t)(b_ * NHEAD + h)) * SEQ + t;
                    if (which == 0) {
                        vx *= QSCALE; vy *= QSCALE;
                        uint32_t hp, lp;
                        split2(vx, vy, hp, lp);
                        size_t base2 = bht * D3 + d;
                        *reinterpret_cast<uint32_t*>(q3 + base2)       = hp;
                        *reinterpret_cast<uint32_t*>(q3 + base2 + 64)  = lp;
                        *reinterpret_cast<uint32_t*>(q3 + base2 + 128) = hp;
                    } else if (which == 1) {
                        float2 o{vx, vy};
                        *reinterpret_cast<float2*>(out0 + bht * HDIM + d) = o;
                        uint32_t hp, lp;
                        split2(vx, vy, hp, lp);
                        size_t base2 = bht * D3 + d;
                        *reinterpret_cast<uint32_t*>(k3 + base2)       = hp;
                        *reinterpret_cast<uint32_t*>(k3 + base2 + 64)  = hp;
                        *reinterpret_cast<uint32_t*>(k3 + base2 + 128) = lp;
                    } else {
                        float2 o{vx, vy};
                        *reinterpret_cast<float2*>(out1 + bht * HDIM + d) = o;
                        uint32_t hp, lp;
                        split2(vx, vy, hp, lp);
                        size_t base2 = bht * 128 + d;
                        *reinterpret_cast<uint32_t*>(v2 + base2)      = hp;
                        *reinterpret_cast<uint32_t*>(v2 + base2 + 64) = lp;
                    }
                }
            }
        }
    }
}

// ---------------------------------------------------------------------------
// HMMA causal flash attention, software-pipelined (FA2-style).
// BM=128 / BN=64, 256 threads (8 warps x 16 q-rows).
// Q3: [B,H,T,192] split (scaled); K3: [B,H,T,192] split; V2: [B,H,T,128] hi|lo.
// Per iter jt: issue S(jt) MMAs, then softmax+PV of tile jt-1 under their shadow.
// 3-stage K ring (3x24K) + 3-stage V ring (3x16K) + Q 48K = 168KB, 1 sync/iter.
// Output: split-bf16 (hi,lo,hi) rows of A3 [M][3072] for the proj GEMM.
// ---------------------------------------------------------------------------
#define QS_OFF   0
#define KS_OFF   49152
#define VS_OFF   122880
#define ATTN_SMEM 172032

__global__ __launch_bounds__(256) void attn_kernel(
    const __nv_bfloat16* __restrict__ Q3, const __nv_bfloat16* __restrict__ K3g,
    const __nv_bfloat16* __restrict__ V2, __nv_bfloat16* __restrict__ Yd)
{
    extern __shared__ char smem[];
    const uint32_t sm = smem_to_u32(smem);
    const uint32_t QS = sm + QS_OFF;
    const uint32_t KS = sm + KS_OFF;
    const uint32_t VS = sm + VS_OFF;

    const int tid = threadIdx.x;
    const int w = tid >> 5;                         // 0..7
    const int lane = tid & 31;
    const int qt = (int)gridDim.x - 1 - (int)blockIdx.x;  // long CTAs first
    const int bh = blockIdx.y;                      // 0..63
    const int qbase = qt * 128;

    const __nv_bfloat16* Qg = Q3 + ((size_t)bh * SEQ + qbase) * D3;
    const __nv_bfloat16* Kg = K3g + (size_t)bh * SEQ * D3;
    const __nv_bfloat16* Vg = V2 + (size_t)bh * SEQ * 128;

    // ---- loaders (256 threads) ----
    auto load_q = [&]() {
        #pragma unroll
        for (int i = 0; i < 12; i++) {
            int g = tid + i * 256;          // 0..3071
            int r = g & 127, bc = g >> 7;   // bc 0..23
            int b = bc >> 3, c = bc & 7;
            const __nv_bfloat16* src = Qg + (size_t)r * D3 + b * 64 + c * 8;
            uint32_t dst = QS + b * 16384 + r * 128 + ((c ^ (r & 7)) << 4);
            CP_ASYNC16(dst, src);
        }
    };
    auto load_k = [&](int jt, int slot) {
        const __nv_bfloat16* base = Kg + (size_t)jt * 64 * D3;
        uint32_t kb = KS + slot * 24576;
        #pragma unroll
        for (int i = 0; i < 6; i++) {
            int g = tid + i * 256;          // 0..1535
            int r = g & 63, bc = g >> 6;    // bc 0..23
            int b = bc >> 3, c = bc & 7;
            const __nv_bfloat16* src = base + (size_t)r * D3 + b * 64 + c * 8;
            uint32_t dst = kb + b * 8192 + r * 128 + ((c ^ (r & 7)) << 4);
            CP_ASYNC16(dst, src);
        }
    };
    auto load_v = [&](int jt, int slot) {
        const __nv_bfloat16* base = Vg + (size_t)jt * 64 * 128;
        uint32_t vb = VS + slot * 16384;    // [VH 8K | VL 8K]
        #pragma unroll
        for (int i = 0; i < 4; i++) {
            int g = tid + i * 256;          // 0..1023
            int r = g >> 4, c = g & 15;
            const __nv_bfloat16* src = base + (size_t)r * 128 + c * 8;
            int cc = c & 7;
            uint32_t half = (c >> 3) * 8192;
            uint32_t dst = vb + half + r * 128 + ((cc ^ (r & 7)) << 4);
            CP_ASYNC16(dst, src);
        }
    };

    float o[8][4];
    #pragma unroll
    for (int j = 0; j < 8; j++)
        #pragma unroll
        for (int q = 0; q < 4; q++) o[j][q] = 0.f;
    float mi0 = -1e30f, mi1 = -1e30f, li0 = 0.f, li1 = 0.f;

    const int jmax = 2 * qt + 1;    // always odd

    // ---- S = Q . K^T over 192 split dims into sd ----
    auto mma_S = [&](float (&sd)[8][4], int slot) {
        #pragma unroll
        for (int j = 0; j < 8; j++)
            #pragma unroll
            for (int q = 0; q < 4; q++) sd[j][q] = 0.f;
        const uint32_t kb = KS + slot * 24576;
        #pragma unroll
        for (int b = 0; b < 3; b++) {
            #pragma unroll
            for (int ks = 0; ks < 4; ks++) {
                uint32_t af[4];
                {
                    int row = w * 16 + (lane & 15);
                    int chunk = 2 * ks + (lane >> 4);
                    ldsm_x4(QS + b * 16384 + row * 128 + ((chunk ^ (row & 7)) << 4), af);
                }
                uint32_t bf[8][2];
                #pragma unroll
                for (int ni = 0; ni < 4; ni++) {
                    int row = ni * 16 + ((lane >> 4) << 3) + (lane & 7);
                    int chunk = 2 * ks + ((lane >> 3) & 1);
                    uint32_t r4[4];
                    ldsm_x4(kb + b * 8192 + row * 128 + ((chunk ^ (row & 7)) << 4), r4);
                    bf[2 * ni][0] = r4[0]; bf[2 * ni][1] = r4[1];
                    bf[2 * ni + 1][0] = r4[2]; bf[2 * ni + 1][1] = r4[3];
                }
                #pragma unroll
                for (int nj = 0; nj < 8; nj++)
                    mma16816(sd[nj], af, bf[nj]);
            }
        }
    };

    // ---- softmax + PV for tile cj (consumes s) ----
    auto consume = [&](float (&s)[8][4], int cj) {
        // causal mask (only where the k-tile can cross the diagonal)
        if (cj * 64 + 63 > qbase + w * 16) {
            const int gr = qbase + w * 16 + (lane >> 2);
            const int cb = cj * 64 + 2 * (lane & 3);
            #pragma unroll
            for (int nj = 0; nj < 8; nj++) {
                int c0 = cb + nj * 8;
                if (c0 > gr)     s[nj][0] = -1e30f;
                if (c0 + 1 > gr) s[nj][1] = -1e30f;
                if (c0 > gr + 8)     s[nj][2] = -1e30f;
                if (c0 + 1 > gr + 8) s[nj][3] = -1e30f;
            }
        }
        // online softmax (base-2; scale folded into Q)
        float mx0 = -1e30f, mx1 = -1e30f;
        #pragma unroll
        for (int nj = 0; nj < 8; nj++) {
            mx0 = fmaxf(mx0, fmaxf(s[nj][0], s[nj][1]));
            mx1 = fmaxf(mx1, fmaxf(s[nj][2], s[nj][3]));
        }
        mx0 = fmaxf(mx0, __shfl_xor_sync(0xffffffffu, mx0, 1));
        mx0 = fmaxf(mx0, __shfl_xor_sync(0xffffffffu, mx0, 2));
        mx1 = fmaxf(mx1, __shfl_xor_sync(0xffffffffu, mx1, 1));
        mx1 = fmaxf(mx1, __shfl_xor_sync(0xffffffffu, mx1, 2));
        float mn0 = fmaxf(mi0, mx0), mn1 = fmaxf(mi1, mx1);
        float c0 = exp2f(mi0 - mn0), c1 = exp2f(mi1 - mn1);
        mi0 = mn0; mi1 = mn1;
        float rs0 = 0.f, rs1 = 0.f;
        #pragma unroll
        for (int nj = 0; nj < 8; nj++) {
            s[nj][0] = exp2f(s[nj][0] - mn0); rs0 += s[nj][0];
            s[nj][1] = exp2f(s[nj][1] - mn0); rs0 += s[nj][1];
            s[nj][2] = exp2f(s[nj][2] - mn1); rs1 += s[nj][2];
            s[nj][3] = exp2f(s[nj][3] - mn1); rs1 += s[nj][3];
        }
        rs0 += __shfl_xor_sync(0xffffffffu, rs0, 1);
        rs0 += __shfl_xor_sync(0xffffffffu, rs0, 2);
        rs1 += __shfl_xor_sync(0xffffffffu, rs1, 1);
        rs1 += __shfl_xor_sync(0xffffffffu, rs1, 2);
        li0 = li0 * c0 + rs0;
        li1 = li1 * c1 + rs1;
        #pragma unroll
        for (int dj = 0; dj < 8; dj++) {
            o[dj][0] *= c0; o[dj][1] *= c0;
            o[dj][2] *= c1; o[dj][3] *= c1;
        }
        // O += P . V  (3-pass split), V from slot cj%3
        const uint32_t vb = VS + (cj % 3) * 16384;
        #pragma unroll
        for (int kc = 0; kc < 4; kc++) {
            uint32_t ah[4], al[4];
            split2(s[2 * kc][0],     s[2 * kc][1],     ah[0], al[0]);
            split2(s[2 * kc][2],     s[2 * kc][3],     ah[1], al[1]);
            split2(s[2 * kc + 1][0], s[2 * kc + 1][1], ah[2], al[2]);
            split2(s[2 * kc + 1][2], s[2 * kc + 1][3], ah[3], al[3]);
            #pragma unroll
            for (int dj2 = 0; dj2 < 4; dj2++) {
                int mm = lane >> 3, j = lane & 7;
                int row = kc * 16 + (mm & 1) * 8 + j;
                int chunk = 2 * dj2 + (mm >> 1);
                uint32_t off = row * 128 + ((chunk ^ (row & 7)) << 4);
                uint32_t bh4[4], bl4[4];
                ldsm_x4_t(vb + off, bh4);
                ldsm_x4_t(vb + 8192 + off, bl4);
                mma16816(o[2 * dj2],     ah, &bh4[0]);
                mma16816(o[2 * dj2 + 1], ah, &bh4[2]);
                mma16816(o[2 * dj2],     al, &bh4[0]);
                mma16816(o[2 * dj2 + 1], al, &bh4[2]);
                mma16816(o[2 * dj2],     ah, &bl4[0]);
                mma16816(o[2 * dj2 + 1], ah, &bl4[2]);
            }
        }
    };

    // ---- one pipelined iteration: produce S(jt) into nxt, consume tile jt-1 ----
    auto iter = [&](int jt, float (&cur)[8][4], float (&nxt)[8][4]) {
        CP_WAIT1();          // group {K[jt], V[jt-1]} complete
        __syncthreads();     // visible to all; all warps done with iter jt-1
        if (jt + 2 <= jmax) load_k(jt + 2, (jt + 2) % 3);
        if (jt + 1 <= jmax) load_v(jt + 1, (jt + 1) % 3);
        CP_COMMIT();
        mma_S(nxt, jt % 3);             // tensor: fills pipe
        if (jt > 0) consume(cur, jt - 1);  // ALU/MUFU under the S shadow, then PV
    };

    // prologue: group P0 = {Q, K0}; P1 = {K1, V0}
    load_q(); load_k(0, 0); CP_COMMIT();
    load_k(1, 1); load_v(0, 0); CP_COMMIT();

    float s0[8][4], s1[8][4];
    for (int jt = 0; jt <= jmax; jt += 2) {
        iter(jt,     s1, s0);   // consume S(jt-1) from s1, produce S(jt) in s0
        iter(jt + 1, s0, s1);   // jmax odd -> always valid
    }
    CP_WAIT0();
    __syncthreads();
    consume(s1, jmax);          // final tile

    // ---- normalize + store split-bf16 (hi,lo,hi) rows of A3 [M][3072] ----
    const int b_ = bh >> 4;
    const int h  = bh & 15;
    const float inv0 = 1.f / li0, inv1 = 1.f / li1;
    const int t0 = qbase + w * 16 + (lane >> 2);
    const int cb = h * HDIM + 2 * (lane & 3);
    const size_t m0 = (size_t)b_ * SEQ + t0;
    #pragma unroll
    for (int dj = 0; dj < 8; dj++) {
        int col = cb + dj * 8;
        uint32_t hp, lp;
        split2(o[dj][0] * inv0, o[dj][1] * inv0, hp, lp);
        __nv_bfloat16* p0 = Yd + m0 * K3 + col;
        *reinterpret_cast<uint32_t*>(p0)        = hp;
        *reinterpret_cast<uint32_t*>(p0 + 1024) = lp;
        *reinterpret_cast<uint32_t*>(p0 + 2048) = hp;
        split2(o[dj][2] * inv1, o[dj][3] * inv1, hp, lp);
        __nv_bfloat16* p1 = Yd + (m0 + 8) * K3 + col;
        *reinterpret_cast<uint32_t*>(p1)        = hp;
        *reinterpret_cast<uint32_t*>(p1 + 1024) = lp;
        *reinterpret_cast<uint32_t*>(p1 + 2048) = hp;
    }
}

// ---------------------------------------------------------------------------
// Launch graph
// d_in: x, Wq, bq, Wk, bk, Wv, bv, Wp, bp
// d_out: [ y | present_k | present_v ]
// ---------------------------------------------------------------------------
extern "C" void kernel_launch(void* const* d_in, const int* in_sizes, int n_in,
                              void* d_out, int out_size)
{
    const float* x  = (const float*)d_in[0];
    const float* Wq = (const float*)d_in[1];
    const float* bq = (const float*)d_in[2];
    const float* Wk = (const float*)d_in[3];
    const float* bk = (const float*)d_in[4];
    const float* Wv = (const float*)d_in[5];
    const float* bv = (const float*)d_in[6];
    const float* Wp = (const float*)d_in[7];
    const float* bp = (const float*)d_in[8];

    float* out  = (float*)d_out;
    float* kout = out + Y_ELEMS;
    float* vout = out + Y_ELEMS + KV_ELEMS;

    __nv_bfloat16 *a3 = nullptr, *w3 = nullptr, *q3 = nullptr, *k3 = nullptr, *v2 = nullptr;
    cudaGetSymbolAddress((void**)&a3, g_a3);
    cudaGetSymbolAddress((void**)&w3, g_w3);
    cudaGetSymbolAddress((void**)&q3, g_q3);
    cudaGetSymbolAddress((void**)&k3, g_k3);
    cudaGetSymbolAddress((void**)&v2, g_v2);

    cudaFuncSetAttribute(gemm_bf16_kernel,
                         cudaFuncAttributeMaxDynamicSharedMemorySize, GSM_TOTAL);
    cudaFuncSetAttribute(attn_kernel,
                         cudaFuncAttributeMaxDynamicSharedMemorySize, ATTN_SMEM);

    const size_t wstride = (size_t)CDIM * K3;
    {
        int total2 = CDIM * 512;
        int blocks = (total2 + 255) / 256;
        conv_split_kernel<<<blocks, 256>>>(Wq, w3 + 0 * wstride, total2, 0);
        conv_split_kernel<<<blocks, 256>>>(Wk, w3 + 1 * wstride, total2, 0);
        conv_split_kernel<<<blocks, 256>>>(Wv, w3 + 2 * wstride, total2, 0);
        conv_split_kernel<<<blocks, 256>>>(Wp, w3 + 3 * wstride, total2, 0);
    }
    {
        int total2 = MROWS * 512;
        conv_split_kernel<<<(total2 + 255) / 256, 256>>>(x, a3, total2, 1);
    }

    // Fused QKV GEMM: N = 3072 over contiguous Wq|Wk|Wv
    gemm_bf16_kernel<<<dim3(24, MROWS / 128), 256, GSM_TOTAL>>>(
        a3, w3, bq, bk, bv, kout, vout, q3, k3, v2, 1);

    // Attention (pipelined, BM=128): writes split-bf16 y rows directly into a3
    attn_kernel<<<dim3(SEQ / 128, BATCH * NHEAD), 256, ATTN_SMEM>>>(q3, k3, v2, a3);

    // Output projection (mode 0)
    gemm_bf16_kernel<<<dim3(8, MROWS / 128), 256, GSM_TOTAL>>>(
        a3, w3 + 3 * wstride, bp, nullptr, nullptr,
        out, nullptr, nullptr, nullptr, nullptr, 0);
}